// round 11
// baseline (speedup 1.0000x reference)
#include <cuda_runtime.h>
#include <cuda_bf16.h>
#include <math.h>

// ---------------- problem constants ----------------
#define DIMN 1024
#define HIDN 2048
#define BB   4
#define SS   2048
#define CHK  64
#define NCH  32        // SS/CHK
#define BC   256       // BB*CHK
#define NTOK 8192      // BB*SS
#define EPSN 1e-8f
#define SCALE_CONST (2.0f/(BB*CHK*DIMN))

using bf = __nv_bfloat16;

// ---------------- device scratch (no runtime allocs allowed) ----------------
__device__ bf g_xh[NTOK*DIMN],  g_xl[NTOK*DIMN];
__device__ bf g_wkh[DIMN*DIMN], g_wkl[DIMN*DIMN];
__device__ bf g_wvh[DIMN*DIMN], g_wvl[DIMN*DIMN];
__device__ bf g_wqh[DIMN*DIMN], g_wql[DIMN*DIMN];
__device__ bf g_woh[DIMN*DIMN], g_wol[DIMN*DIMN];
__device__ float g_kp[NCH*BC*DIMN];
__device__ float g_qp[NCH*BC*DIMN];
__device__ bf g_kph[NCH*BC*DIMN], g_kpl[NCH*BC*DIMN];
__device__ bf g_qph[NCH*BC*DIMN], g_qpl[NCH*BC*DIMN];
__device__ bf g_vph[NCH*BC*DIMN], g_vpl[NCH*BC*DIMN];
__device__ float g_h1[BC*HIDN];
__device__ bf g_a1h[BC*HIDN], g_a1l[BC*HIDN];
__device__ bf g_d2h[BC*DIMN], g_d2l[BC*DIMN];
__device__ bf g_d1h[BC*HIDN], g_d1l[BC*HIDN];
__device__ bf g_aqh[BC*HIDN], g_aql[BC*HIDN];
__device__ bf g_yh[NTOK*DIMN], g_yl[NTOK*DIMN];
__device__ float g_w1f[2][HIDN*DIMN];
__device__ bf    g_w1h[2][HIDN*DIMN], g_w1l[2][HIDN*DIMN];
__device__ float g_w2f[2][DIMN*HIDN];
__device__ bf    g_w2h[2][DIMN*HIDN], g_w2l[2][DIMN*HIDN];
__device__ float g_m1[HIDN*DIMN];
__device__ float g_m2[DIMN*HIDN];
__device__ float g_gate_tok[NTOK*3];
__device__ float g_gates[NCH*3];

// ---------------- math helpers ----------------
__device__ __forceinline__ float sigf(float x){ return 1.0f/(1.0f+expf(-x)); }
__device__ __forceinline__ float siluf(float x){ return x*sigf(x); }
__device__ __forceinline__ float siluderivf(float x){ float s=sigf(x); return s*(1.0f + x*(1.0f-s)); }
__device__ __forceinline__ float clip1f(float x){ return fminf(fmaxf(x,-1.0f),1.0f); }
__device__ __forceinline__ void store_hl(bf* H, bf* L, size_t idx, float v){
    bf h = __float2bfloat16_rn(v);
    H[idx] = h;
    L[idx] = __float2bfloat16_rn(v - __bfloat162float(h));
}

// ---------------- mma / ldmatrix / cp.async primitives ----------------
__device__ __forceinline__ void mma_bf16(float* d, const unsigned* a, const unsigned* b){
    asm volatile(
        "mma.sync.aligned.m16n8k16.row.col.f32.bf16.bf16.f32 "
        "{%0,%1,%2,%3}, {%4,%5,%6,%7}, {%8,%9}, {%0,%1,%2,%3};\n"
        : "+f"(d[0]), "+f"(d[1]), "+f"(d[2]), "+f"(d[3])
        : "r"(a[0]), "r"(a[1]), "r"(a[2]), "r"(a[3]), "r"(b[0]), "r"(b[1]));
}
__device__ __forceinline__ void ldsm4(unsigned* r, const bf* p){
    unsigned a = (unsigned)__cvta_generic_to_shared(p);
    asm volatile("ldmatrix.sync.aligned.m8n8.x4.shared.b16 {%0,%1,%2,%3}, [%4];\n"
        : "=r"(r[0]), "=r"(r[1]), "=r"(r[2]), "=r"(r[3]) : "r"(a));
}
__device__ __forceinline__ void cpa16(bf* s, const bf* g){
    unsigned sa = (unsigned)__cvta_generic_to_shared(s);
    asm volatile("cp.async.cg.shared.global [%0], [%1], 16;\n" :: "r"(sa), "l"(g));
}
__device__ __forceinline__ void cp_commit(){ asm volatile("cp.async.commit_group;\n"); }
template<int N> __device__ __forceinline__ void cp_wait(){ asm volatile("cp.async.wait_group %0;\n" :: "n"(N)); }

// ---------------- register-staged loader (KM=false transpose path) ----------------
template<int R, bool KM, int KC, int KS>
struct Loader {
    static constexpr int TOT = (R*KC)/8;          // 16B chunks per array
    static constexpr int CH  = (TOT + 127)/128;
    uint4 vh[CH], vl[CH];
    __device__ __forceinline__ void fetch(const bf* __restrict__ Ph, const bf* __restrict__ Pl,
                                          int ld, int r0, int k0, int tid){
        #pragma unroll
        for (int c = 0; c < CH; ++c){
            int id = tid + c*128;
            if ((TOT % 128 == 0) || id < TOT){
                if constexpr (KM){
                    int r = id/(KC/8), kq = (id%(KC/8))*8;
                    size_t off = (size_t)(r0+r)*ld + k0 + kq;
                    vh[c] = *(const uint4*)(Ph + off);
                    vl[c] = *(const uint4*)(Pl + off);
                } else {
                    int k = id/(R/8), rq = (id%(R/8))*8;
                    size_t off = (size_t)(k0+k)*ld + r0 + rq;
                    vh[c] = *(const uint4*)(Ph + off);
                    vl[c] = *(const uint4*)(Pl + off);
                }
            }
        }
    }
    __device__ __forceinline__ void store(bf* Sh, bf* Sl, int tid){
        #pragma unroll
        for (int c = 0; c < CH; ++c){
            int id = tid + c*128;
            if ((TOT % 128 == 0) || id < TOT){
                if constexpr (KM){
                    int r = id/(KC/8), kq = (id%(KC/8))*8;
                    *(uint4*)(Sh + r*KS + kq) = vh[c];
                    *(uint4*)(Sl + r*KS + kq) = vl[c];
                } else {
                    int k = id/(R/8), rq = (id%(R/8))*8;
                    const bf* ph = (const bf*)&vh[c];
                    const bf* pl = (const bf*)&vl[c];
                    #pragma unroll
                    for (int j = 0; j < 8; ++j){
                        Sh[(rq+j)*KS + k] = ph[j];
                        Sl[(rq+j)*KS + k] = pl[j];
                    }
                }
            }
        }
    }
};

// ---------------- GEMM core: C[M,N] = sum_k A(m,k)*B(n,k) ----------------
// BM in {16,32,64}. BM=16: 4 warps, each one 16x16 m-frag (MI=1,NI=2).
// EP: 0 C=acc | 1 C=acc,Ch/Cl=silu | 2 Ch/Cl=scale*clip(acc-(x0h+x0l)) | 3 Ch/Cl=acc*silu'(f0)
//     4 weight update | 5 Ch/Cl=silu | 6 Ch/Cl=acc natural-layout | 7 C=silu perm | 8 Ch/Cl=silu perm
template<int BM,int BN,bool AKM,bool BKM,int EP>
__device__ __forceinline__ void mgemm_core(
    char* dsm,
    const bf* __restrict__ Ah, const bf* __restrict__ Al, int lda,
    const bf* __restrict__ Bh, const bf* __restrict__ Bl, int ldb,
    float* __restrict__ C, bf* __restrict__ Ch, bf* __restrict__ Cl, int ldc,
    int K,
    const float* __restrict__ f0,
    const bf* __restrict__ x0h, const bf* __restrict__ x0l,
    float* __restrict__ f1,
    const float* __restrict__ gates,
    float scale, int base, int m0, int n0)
{
    constexpr int KC = 32;
    constexpr int KS = 40;
    constexpr int MI = (BM >= 32) ? 2 : 1;
    constexpr int NI = (BM == 64) ? 4 : 2;
    constexpr int NJ = NI/2;
    constexpr int ASZ = BM*KS, BSZ = BN*KS;
    constexpr int STRIDE = 2*ASZ + 2*BSZ;

    const int tid  = threadIdx.x;
    const int lane = tid & 31;
    const int wid  = tid >> 5;
    const int g    = lane >> 2;
    const int tg   = lane & 3;
    const int wm = (BM == 64) ? (wid >> 1) * 32 : 0;
    const int wn = (BM == 64) ? (wid & 1) * 32 : wid * 16;
    const int aoff = (lane & 15)*KS + (lane >> 4)*8;
    const int boff = ((lane & 7) + ((lane >> 4) & 1)*8)*KS + ((lane >> 3) & 1)*8;

    bf* base_s = (bf*)dsm;

    float accm[MI][NI][4] = {};
    float accc[MI][NI][4] = {};

    auto compute_tile = [&](const bf* Ahs, const bf* Als, const bf* Bhs, const bf* Bls){
        #pragma unroll
        for (int kt = 0; kt < KC; kt += 16) {
            unsigned ah[MI][4], al_[MI][4], b2h[NJ][4], b2l[NJ][4];
            #pragma unroll
            for (int mi = 0; mi < MI; ++mi) {
                ldsm4(ah[mi],  Ahs + (wm + mi*16)*KS + kt + aoff);
                ldsm4(al_[mi], Als + (wm + mi*16)*KS + kt + aoff);
            }
            #pragma unroll
            for (int nj = 0; nj < NJ; ++nj) {
                ldsm4(b2h[nj], Bhs + (wn + nj*16)*KS + kt + boff);
                ldsm4(b2l[nj], Bls + (wn + nj*16)*KS + kt + boff);
            }
            #pragma unroll
            for (int mi = 0; mi < MI; ++mi)
                #pragma unroll
                for (int nj = 0; nj < NJ; ++nj) {
                    mma_bf16(accm[mi][nj*2+0], ah[mi],  b2h[nj]+0);
                    mma_bf16(accm[mi][nj*2+1], ah[mi],  b2h[nj]+2);
                    mma_bf16(accc[mi][nj*2+0], ah[mi],  b2l[nj]+0);
                    mma_bf16(accc[mi][nj*2+1], ah[mi],  b2l[nj]+2);
                    mma_bf16(accc[mi][nj*2+0], al_[mi], b2h[nj]+0);
                    mma_bf16(accc[mi][nj*2+1], al_[mi], b2h[nj]+2);
                }
        }
    };

    if constexpr (AKM && BKM) {
        // ---- 4-stage cp.async pipeline ----
        constexpr int STG = 4;
        constexpr int ATOT = BM*KC/8;   // 16B chunks for A
        constexpr int BTOT = BN*KC/8;
        const int KT = K / KC;
        auto issue = [&](int s, int k0){
            bf* dAh = base_s + s*STRIDE; bf* dAl = dAh + ASZ;
            bf* dBh = dAl + ASZ;         bf* dBl = dBh + BSZ;
            #pragma unroll
            for (int c2 = 0; c2 < (ATOT+127)/128; ++c2){
                int id = tid + c2*128;
                if ((ATOT % 128 == 0) || id < ATOT){
                    int r = id >> 2, kq = (id & 3)*8;
                    size_t off = (size_t)(m0+r)*lda + k0 + kq;
                    cpa16(dAh + r*KS + kq, Ah + off);
                    cpa16(dAl + r*KS + kq, Al + off);
                }
            }
            #pragma unroll
            for (int c2 = 0; c2 < (BTOT+127)/128; ++c2){
                int id = tid + c2*128;
                if ((BTOT % 128 == 0) || id < BTOT){
                    int r = id >> 2, kq = (id & 3)*8;
                    size_t off = (size_t)(n0+r)*ldb + k0 + kq;
                    cpa16(dBh + r*KS + kq, Bh + off);
                    cpa16(dBl + r*KS + kq, Bl + off);
                }
            }
            cp_commit();
        };
        int fetch = 0;
        for (; fetch < STG-1 && fetch < KT; ++fetch) issue(fetch, fetch*KC);
        for (int c = 0; c < KT; ++c){
            int nrem = fetch - 1 - c;          // pending groups allowed so group c is complete
            if (nrem >= 2) cp_wait<2>(); else if (nrem == 1) cp_wait<1>(); else cp_wait<0>();
            __syncthreads();
            if (fetch < KT){ issue(fetch % STG, fetch*KC); ++fetch; }
            int s = c % STG;
            bf* pAh = base_s + s*STRIDE; bf* pAl = pAh + ASZ;
            bf* pBh = pAl + ASZ;         bf* pBl = pBh + BSZ;
            compute_tile(pAh, pAl, pBh, pBl);
        }
    } else {
        // ---- register-staged 2-buffer path (handles transpose loads) ----
        Loader<BM,AKM,KC,KS> la;
        Loader<BN,BKM,KC,KS> lb;
        bf* A0[2]; bf* A1[2]; bf* B0[2]; bf* B1[2];
        #pragma unroll
        for (int b = 0; b < 2; ++b){
            bf* p = base_s + b*STRIDE;
            A0[b] = p; A1[b] = p + ASZ; B0[b] = p + 2*ASZ; B1[b] = p + 2*ASZ + BSZ;
        }
        la.fetch(Ah, Al, lda, m0, 0, tid);
        lb.fetch(Bh, Bl, ldb, n0, 0, tid);
        la.store(A0[0], A1[0], tid);
        lb.store(B0[0], B1[0], tid);
        __syncthreads();
        int cur = 0;
        for (int k0 = 0; k0 < K; k0 += KC) {
            bool more = (k0 + KC) < K;
            if (more) {
                la.fetch(Ah, Al, lda, m0, k0 + KC, tid);
                lb.fetch(Bh, Bl, ldb, n0, k0 + KC, tid);
            }
            compute_tile(A0[cur], A1[cur], B0[cur], B1[cur]);
            if (more) {
                la.store(A0[cur^1], A1[cur^1], tid);
                lb.store(B0[cur^1], B1[cur^1], tid);
                __syncthreads();
                cur ^= 1;
            }
        }
    }

    // ---- epilogue ----
    float lrg = 0.f, alg = 0.f, etg = 0.f;
    if constexpr (EP == 4) { lrg = gates[0]; alg = gates[1]; etg = gates[2]; }

    #pragma unroll
    for (int mi = 0; mi < MI; ++mi)
    #pragma unroll
    for (int rr = 0; rr < 2; ++rr) {
        int m = m0 + wm + mi*16 + rr*8 + g;
        size_t crow;
        if constexpr (EP == 6) {
            int b = m >> 6, ci = m & 63;
            crow = (size_t)(b*SS + base + ci) * ldc;
        } else if constexpr (EP == 7 || EP == 8) {
            int b = m >> 11, s = m & (SS-1);
            crow = (size_t)((s >> 6)*BC + b*CHK + (s & 63)) * ldc;
        } else {
            crow = (size_t)m * ldc;
        }
        size_t srow = (size_t)m * ldc;
        #pragma unroll
        for (int ni = 0; ni < NI; ++ni) {
            int n = n0 + wn + ni*8 + tg*2;
            #pragma unroll
            for (int cc = 0; cc < 2; ++cc) {
                float v = accm[mi][ni][rr*2 + cc] + accc[mi][ni][rr*2 + cc];
                size_t idx  = crow + n + cc;
                size_t sidx = srow + n + cc;
                if constexpr (EP == 0) C[idx] = v;
                else if constexpr (EP == 1) { C[idx] = v; store_hl(Ch, Cl, idx, siluf(v)); }
                else if constexpr (EP == 2) {
                    float vv = __bfloat162float(x0h[sidx]) + __bfloat162float(x0l[sidx]);
                    store_hl(Ch, Cl, idx, scale * clip1f(v - vv));
                }
                else if constexpr (EP == 3) store_hl(Ch, Cl, idx, v * siluderivf(f0[sidx]));
                else if constexpr (EP == 4) {
                    float gg = clip1f(v);
                    float mn = etg * f1[idx] - lrg * gg;
                    f1[idx] = mn;
                    float w = (1.0f - alg) * f0[idx] + mn;
                    C[idx] = w;
                    store_hl(Ch, Cl, idx, w);
                }
                else if constexpr (EP == 5) store_hl(Ch, Cl, idx, siluf(v));
                else if constexpr (EP == 6) store_hl(Ch, Cl, idx, v);
                else if constexpr (EP == 7) C[idx] = siluf(v);
                else if constexpr (EP == 8) store_hl(Ch, Cl, idx, siluf(v));
            }
        }
    }
}

template<int BM,int BN,bool AKM,bool BKM,int EP>
__global__ __launch_bounds__(128,2)
void mgemm_k(const bf* __restrict__ Ah, const bf* __restrict__ Al, int lda,
             const bf* __restrict__ Bh, const bf* __restrict__ Bl, int ldb,
             float* __restrict__ C, bf* __restrict__ Ch, bf* __restrict__ Cl, int ldc,
             int K,
             const float* __restrict__ f0,
             const bf* __restrict__ x0h, const bf* __restrict__ x0l,
             float* __restrict__ f1,
             const float* __restrict__ gates, float scale, int base)
{
    extern __shared__ __align__(16) char dsm[];
    mgemm_core<BM,BN,AKM,BKM,EP>(dsm, Ah,Al,lda, Bh,Bl,ldb, C,Ch,Cl,ldc, K,
                                 f0,x0h,x0l,f1, gates, scale, base,
                                 blockIdx.y*BM, blockIdx.x*BN);
}

// fused weight updates (w2 grad + w1 grad), both EP4, 64x64 tiles, K=BC
__global__ __launch_bounds__(128,2)
void wupd_k(const bf* __restrict__ d2h, const bf* __restrict__ d2l,
            const bf* __restrict__ a1h, const bf* __restrict__ a1l,
            float* __restrict__ w2n, bf* __restrict__ w2nh, bf* __restrict__ w2nl,
            const float* __restrict__ w2o, float* __restrict__ m2,
            const bf* __restrict__ d1h, const bf* __restrict__ d1l,
            const bf* __restrict__ kth, const bf* __restrict__ ktl,
            float* __restrict__ w1n, bf* __restrict__ w1nh, bf* __restrict__ w1nl,
            const float* __restrict__ w1o, float* __restrict__ m1,
            const float* __restrict__ gates)
{
    extern __shared__ __align__(16) char dsm[];
    int bx = blockIdx.x;
    constexpr int T2 = (HIDN/64)*(DIMN/64);
    if (bx < T2) {
        int nt = bx % (HIDN/64), mt = bx / (HIDN/64);
        mgemm_core<64,64,false,false,4>(dsm, d2h,d2l,DIMN, a1h,a1l,HIDN,
                                        w2n,w2nh,w2nl,HIDN, BC,
                                        w2o,nullptr,nullptr,m2, gates, 0.f, 0,
                                        mt*64, nt*64);
    } else {
        int i = bx - T2;
        int nt = i % (DIMN/64), mt = i / (DIMN/64);
        mgemm_core<64,64,false,false,4>(dsm, d1h,d1l,HIDN, kth,ktl,DIMN,
                                        w1n,w1nh,w1nl,DIMN, BC,
                                        w1o,nullptr,nullptr,m1, gates, 0.f, 0,
                                        mt*64, nt*64);
    }
}

// ---------------- fp32 -> bf16 hi/lo pre-split ----------------
__global__ void split_k(const float* __restrict__ s, bf* __restrict__ h, bf* __restrict__ l, int n)
{
    int i = (blockIdx.x*256 + threadIdx.x)*4;
    if (i >= n) return;
    float4 v = *(const float4*)(s + i);
    float f[4] = {v.x, v.y, v.z, v.w};
    bf hv[4], lv[4];
    #pragma unroll
    for (int j = 0; j < 4; ++j) {
        hv[j] = __float2bfloat16_rn(f[j]);
        lv[j] = __float2bfloat16_rn(f[j] - __bfloat162float(hv[j]));
    }
    *(uint2*)(h + i) = *(uint2*)hv;
    *(uint2*)(l + i) = *(uint2*)lv;
}

// ---------------- l2 normalize fp32 row -> hi/lo bf16 ----------------
__global__ void l2norm_k(const float* __restrict__ src, bf* __restrict__ h, bf* __restrict__ l)
{
    int row = blockIdx.x;
    const float* r = src + (size_t)row * DIMN;
    int t = threadIdx.x;
    float4 v = *(const float4*)(r + t*4);
    float ss = v.x*v.x + v.y*v.y + v.z*v.z + v.w*v.w;
    __shared__ float red[256];
    red[t] = ss; __syncthreads();
    for (int o = 128; o > 0; o >>= 1) { if (t < o) red[t] += red[t+o]; __syncthreads(); }
    float inv = rsqrtf(red[0] + EPSN);
    float f[4] = {v.x*inv, v.y*inv, v.z*inv, v.w*inv};
    bf hv[4], lv[4];
    #pragma unroll
    for (int j = 0; j < 4; ++j) {
        hv[j] = __float2bfloat16_rn(f[j]);
        lv[j] = __float2bfloat16_rn(f[j] - __bfloat162float(hv[j]));
    }
    size_t o4 = (size_t)row * DIMN + t*4;
    *(uint2*)(h + o4) = *(uint2*)hv;
    *(uint2*)(l + o4) = *(uint2*)lv;
}

// ---------------- per-token gate dots ----------------
__global__ void gate_tok_k(const float* __restrict__ x,
                           const float* __restrict__ wlr,  const float* __restrict__ blr,
                           const float* __restrict__ wdec, const float* __restrict__ bdec,
                           const float* __restrict__ wmom, const float* __restrict__ bmom)
{
    int tok = blockIdx.x;
    int t = threadIdx.x;
    const float* xr = x + (size_t)tok * DIMN;
    float s0 = 0.f, s1 = 0.f, s2 = 0.f;
    for (int i = t; i < DIMN; i += 256) {
        float xi = xr[i];
        s0 += xi * wlr[i]; s1 += xi * wdec[i]; s2 += xi * wmom[i];
    }
    __shared__ float r0[256], r1[256], r2[256];
    r0[t] = s0; r1[t] = s1; r2[t] = s2; __syncthreads();
    for (int o = 128; o > 0; o >>= 1) {
        if (t < o) { r0[t] += r0[t+o]; r1[t] += r1[t+o]; r2[t] += r2[t+o]; }
        __syncthreads();
    }
    if (t == 0) {
        g_gate_tok[tok*3+0] = sigf(r0[0] + blr[0]);
        g_gate_tok[tok*3+1] = sigf(r1[0] + bdec[0]);
        g_gate_tok[tok*3+2] = sigf(r2[0] + bmom[0]);
    }
}

// ---------------- per-chunk gate means ----------------
__global__ void gate_chunk_k()
{
    int ch = blockIdx.x;
    int t = threadIdx.x;
    int b = t >> 6, ci = t & 63;
    int tok = b*SS + ch*CHK + ci;
    __shared__ float r0[256], r1[256], r2[256];
    r0[t] = g_gate_tok[tok*3+0];
    r1[t] = g_gate_tok[tok*3+1];
    r2[t] = g_gate_tok[tok*3+2];
    __syncthreads();
    for (int o = 128; o > 0; o >>= 1) {
        if (t < o) { r0[t] += r0[t+o]; r1[t] += r1[t+o]; r2[t] += r2[t+o]; }
        __syncthreads();
    }
    if (t == 0) {
        g_gates[ch*3+0] = r0[0] * (1.0f/BC);
        g_gates[ch*3+1] = r1[0] * (1.0f/BC);
        g_gates[ch*3+2] = r2[0] * (1.0f/BC);
    }
}

// smem sizes per config
#define SM_A64 (4*(2*64+2*64)*40*2)   // 81920  (64x64 cp.async, 4 stages)
#define SM_A16 (4*(2*16+2*64)*40*2)   // 51200  (16x64 cp.async, 4 stages)
#define SM_R16 (2*(2*16+2*64)*40*2)   // 25600  (16x64 reg path)
#define SM_R64 (2*(2*64+2*64)*40*2)   // 40960  (64x64 reg path / wupd)

// ---------------- host orchestration ----------------
extern "C" void kernel_launch(void* const* d_in, const int* in_sizes, int n_in,
                              void* d_out, int out_size)
{
    const float* x    = (const float*)d_in[0];
    const float* Wk   = (const float*)d_in[1];
    const float* Wv   = (const float*)d_in[2];
    const float* Wq   = (const float*)d_in[3];
    const float* Wout = (const float*)d_in[4];
    const float* W1   = (const float*)d_in[5];
    const float* W2   = (const float*)d_in[6];
    const float* Wlr  = (const float*)d_in[7];
    const float* blr  = (const float*)d_in[8];
    const float* Wdec = (const float*)d_in[9];
    const float* bdec = (const float*)d_in[10];
    const float* Wmom = (const float*)d_in[11];
    const float* bmom = (const float*)d_in[12];
    float* out = (float*)d_out;

    static cudaStream_t s2 = nullptr;
    static cudaEvent_t evA = nullptr, evB0 = nullptr, evB1 = nullptr;
    if (!s2) {
        cudaStreamCreateWithFlags(&s2, cudaStreamNonBlocking);
        cudaEventCreateWithFlags(&evA,  cudaEventDisableTiming);
        cudaEventCreateWithFlags(&evB0, cudaEventDisableTiming);
        cudaEventCreateWithFlags(&evB1, cudaEventDisableTiming);
        cudaFuncSetAttribute(mgemm_k<64,64,true,true,7>, cudaFuncAttributeMaxDynamicSharedMemorySize, SM_A64);
        cudaFuncSetAttribute(mgemm_k<64,64,true,true,8>, cudaFuncAttributeMaxDynamicSharedMemorySize, SM_A64);
        cudaFuncSetAttribute(mgemm_k<64,64,true,true,0>, cudaFuncAttributeMaxDynamicSharedMemorySize, SM_A64);
        cudaFuncSetAttribute(mgemm_k<16,64,true,true,1>, cudaFuncAttributeMaxDynamicSharedMemorySize, SM_A16);
        cudaFuncSetAttribute(mgemm_k<16,64,true,true,2>, cudaFuncAttributeMaxDynamicSharedMemorySize, SM_A16);
        cudaFuncSetAttribute(mgemm_k<16,64,true,true,5>, cudaFuncAttributeMaxDynamicSharedMemorySize, SM_A16);
        cudaFuncSetAttribute(mgemm_k<16,64,true,true,6>, cudaFuncAttributeMaxDynamicSharedMemorySize, SM_A16);
    }

    bf *xh,*xl,*wkh,*wkl,*wvh,*wvl,*wqh,*wql,*woh,*wol;
    bf *kph,*kpl,*qph,*qpl,*vph,*vpl;
    bf *a1h,*a1l,*d2h,*d2l,*d1h,*d1l,*aqh,*aql,*yh,*yl;
    float *kp,*qp,*h1,*m1,*m2,*gch;
    float *w1f0,*w1f1,*w2f0,*w2f1;
    bf *w1h0,*w1h1,*w1l0,*w1l1,*w2h0,*w2h1,*w2l0,*w2l1;

    cudaGetSymbolAddress((void**)&xh, g_xh);   cudaGetSymbolAddress((void**)&xl, g_xl);
    cudaGetSymbolAddress((void**)&wkh,g_wkh);  cudaGetSymbolAddress((void**)&wkl,g_wkl);
    cudaGetSymbolAddress((void**)&wvh,g_wvh);  cudaGetSymbolAddress((void**)&wvl,g_wvl);
    cudaGetSymbolAddress((void**)&wqh,g_wqh);  cudaGetSymbolAddress((void**)&wql,g_wql);
    cudaGetSymbolAddress((void**)&woh,g_woh);  cudaGetSymbolAddress((void**)&wol,g_wol);
    cudaGetSymbolAddress((void**)&kp, g_kp);   cudaGetSymbolAddress((void**)&qp, g_qp);
    cudaGetSymbolAddress((void**)&kph,g_kph);  cudaGetSymbolAddress((void**)&kpl,g_kpl);
    cudaGetSymbolAddress((void**)&qph,g_qph);  cudaGetSymbolAddress((void**)&qpl,g_qpl);
    cudaGetSymbolAddress((void**)&vph,g_vph);  cudaGetSymbolAddress((void**)&vpl,g_vpl);
    cudaGetSymbolAddress((void**)&h1, g_h1);
    cudaGetSymbolAddress((void**)&a1h,g_a1h);  cudaGetSymbolAddress((void**)&a1l,g_a1l);
    cudaGetSymbolAddress((void**)&d2h,g_d2h);  cudaGetSymbolAddress((void**)&d2l,g_d2l);
    cudaGetSymbolAddress((void**)&d1h,g_d1h);  cudaGetSymbolAddress((void**)&d1l,g_d1l);
    cudaGetSymbolAddress((void**)&aqh,g_aqh);  cudaGetSymbolAddress((void**)&aql,g_aql);
    cudaGetSymbolAddress((void**)&yh, g_yh);   cudaGetSymbolAddress((void**)&yl, g_yl);
    cudaGetSymbolAddress((void**)&m1, g_m1);   cudaGetSymbolAddress((void**)&m2, g_m2);
    cudaGetSymbolAddress((void**)&gch,g_gates);
    { void* p;
      cudaGetSymbolAddress(&p, g_w1f); w1f0=(float*)p; w1f1=w1f0+HIDN*DIMN;
      cudaGetSymbolAddress(&p, g_w1h); w1h0=(bf*)p;    w1h1=w1h0+HIDN*DIMN;
      cudaGetSymbolAddress(&p, g_w1l); w1l0=(bf*)p;    w1l1=w1l0+HIDN*DIMN;
      cudaGetSymbolAddress(&p, g_w2f); w2f0=(float*)p; w2f1=w2f0+DIMN*HIDN;
      cudaGetSymbolAddress(&p, g_w2h); w2h0=(bf*)p;    w2h1=w2h0+DIMN*HIDN;
      cudaGetSymbolAddress(&p, g_w2l); w2l0=(bf*)p;    w2l1=w2l0+DIMN*HIDN;
    }

    cudaMemsetAsync(m1, 0, sizeof(float)*HIDN*DIMN);
    cudaMemsetAsync(m2, 0, sizeof(float)*DIMN*HIDN);

    // pre-split inputs
    split_k<<<(NTOK*DIMN)/1024, 256>>>(x,    xh,  xl,  NTOK*DIMN);
    split_k<<<(DIMN*DIMN)/1024, 256>>>(Wk,   wkh, wkl, DIMN*DIMN);
    split_k<<<(DIMN*DIMN)/1024, 256>>>(Wv,   wvh, wvl, DIMN*DIMN);
    split_k<<<(DIMN*DIMN)/1024, 256>>>(Wq,   wqh, wql, DIMN*DIMN);
    split_k<<<(DIMN*DIMN)/1024, 256>>>(Wout, woh, wol, DIMN*DIMN);
    split_k<<<(HIDN*DIMN)/1024, 256>>>(W1,   w1h1, w1l1, HIDN*DIMN);
    split_k<<<(DIMN*HIDN)/1024, 256>>>(W2,   w2h1, w2l1, DIMN*HIDN);

    gate_tok_k<<<NTOK, 256>>>(x, Wlr, blr, Wdec, bdec, Wmom, bmom);
    gate_chunk_k<<<NCH, 256>>>();

    // projections
    dim3 gproj(DIMN/64, NTOK/64);
    mgemm_k<64,64,true,true,7><<<gproj,128,SM_A64>>>(xh,xl,DIMN, wkh,wkl,DIMN, kp,nullptr,nullptr,DIMN, DIMN, nullptr,nullptr,nullptr,nullptr, nullptr,0.f,0);
    mgemm_k<64,64,true,true,7><<<gproj,128,SM_A64>>>(xh,xl,DIMN, wqh,wql,DIMN, qp,nullptr,nullptr,DIMN, DIMN, nullptr,nullptr,nullptr,nullptr, nullptr,0.f,0);
    mgemm_k<64,64,true,true,8><<<gproj,128,SM_A64>>>(xh,xl,DIMN, wvh,wvl,DIMN, nullptr,vph,vpl,DIMN, DIMN, nullptr,nullptr,nullptr,nullptr, nullptr,0.f,0);
    l2norm_k<<<NTOK,256>>>(kp, kph, kpl);
    l2norm_k<<<NTOK,256>>>(qp, qph, qpl);

    for (int ch = 0; ch < NCH; ++ch) {
        size_t co = (size_t)ch*BC*DIMN;
        const bf *kth = kph+co, *ktl = kpl+co;
        const bf *qth = qph+co, *qtl = qpl+co;
        const bf *vth = vph+co, *vtl = vpl+co;
        int wi = ch & 1;
        int ri = 1 - wi;
        const float* w1o = (ch == 0) ? W1 : (ri ? w1f1 : w1f0);
        const float* w2o = (ch == 0) ? W2 : (ri ? w2f1 : w2f0);
        const bf *w1rh = ri ? w1h1 : w1h0, *w1rl = ri ? w1l1 : w1l0;
        const bf *w2rh = ri ? w2h1 : w2h0, *w2rl = ri ? w2l1 : w2l0;
        float* w1n = wi ? w1f1 : w1f0;
        float* w2n = wi ? w2f1 : w2f0;
        bf *w1nh = wi ? w1h1 : w1h0, *w1nl = wi ? w1l1 : w1l0;
        bf *w2nh = wi ? w2h1 : w2h0, *w2nl = wi ? w2l1 : w2l0;
        const float* gp3 = gch + ch*3;

        // forward + grads on stream 0 (BM=16 tiles: 2x block parallelism)
        mgemm_k<16,64,true,true,1><<<dim3(HIDN/64, BC/16),128,SM_A16>>>(
            kth,ktl,DIMN, w1rh,w1rl,DIMN, h1,a1h,a1l,HIDN, DIMN,
            nullptr,nullptr,nullptr,nullptr, nullptr,0.f,0);
        mgemm_k<16,64,true,true,2><<<dim3(DIMN/64, BC/16),128,SM_A16>>>(
            a1h,a1l,HIDN, w2rh,w2rl,HIDN, nullptr,d2h,d2l,DIMN, HIDN,
            nullptr,vth,vtl,nullptr, nullptr,SCALE_CONST,0);
        mgemm_k<16,64,true,false,3><<<dim3(HIDN/64, BC/16),128,SM_R16>>>(
            d2h,d2l,DIMN, w2rh,w2rl,HIDN, nullptr,d1h,d1l,HIDN, DIMN,
            h1,nullptr,nullptr,nullptr, nullptr,0.f,0);
        // wupd(ch) rewrites weight slot (ch&1): wait until retrieval of ch-2 (same slot) finished
        if (ch >= 2) cudaStreamWaitEvent(0, (ch & 1) ? evB1 : evB0, 0);
        wupd_k<<<(HIDN/64)*(DIMN/64)*2,128,SM_R64>>>(
            d2h,d2l, a1h,a1l, w2n,w2nh,w2nl, w2o,m2,
            d1h,d1l, kth,ktl, w1n,w1nh,w1nl, w1o,m1, gp3);
        // retrieval on stream 2, overlapped with next chunk's forward
        cudaEventRecord(evA, 0);
        cudaStreamWaitEvent(s2, evA, 0);
        mgemm_k<16,64,true,true,5><<<dim3(HIDN/64, BC/16),128,SM_A16,s2>>>(
            qth,qtl,DIMN, w1nh,w1nl,DIMN, nullptr,aqh,aql,HIDN, DIMN,
            nullptr,nullptr,nullptr,nullptr, nullptr,0.f,0);
        mgemm_k<16,64,true,true,6><<<dim3(DIMN/64, BC/16),128,SM_A16,s2>>>(
            aqh,aql,HIDN, w2nh,w2nl,HIDN, nullptr,yh,yl,DIMN, HIDN,
            nullptr,nullptr,nullptr,nullptr, nullptr,0.f,ch*CHK);
        cudaEventRecord((ch & 1) ? evB1 : evB0, s2);
    }

    // join retrieval stream, then output projection
    cudaStreamWaitEvent(0, ((NCH-1) & 1) ? evB1 : evB0, 0);
    mgemm_k<64,64,true,true,0><<<dim3(DIMN/64, NTOK/64),128,SM_A64>>>(
        yh,yl,DIMN, woh,wol,DIMN, out,nullptr,nullptr,DIMN, DIMN,
        nullptr,nullptr,nullptr,nullptr, nullptr,0.f,0);
}

// round 14
// speedup vs baseline: 1.2000x; 1.2000x over previous
#include <cuda_runtime.h>
#include <cuda_bf16.h>
#include <math.h>

// ---------------- problem constants ----------------
#define DIMN 1024
#define HIDN 2048
#define BB   4
#define SS   2048
#define CHK  64
#define NCH  32        // SS/CHK
#define BC   256       // BB*CHK
#define NTOK 8192      // BB*SS
#define EPSN 1e-8f
#define SCALE_CONST (2.0f/(BB*CHK*DIMN))

using bf = __nv_bfloat16;

// ---------------- device scratch (no runtime allocs allowed) ----------------
__device__ bf g_xh[NTOK*DIMN],  g_xl[NTOK*DIMN];
__device__ bf g_wkh[DIMN*DIMN], g_wkl[DIMN*DIMN];
__device__ bf g_wvh[DIMN*DIMN], g_wvl[DIMN*DIMN];
__device__ bf g_wqh[DIMN*DIMN], g_wql[DIMN*DIMN];
__device__ bf g_woh[DIMN*DIMN], g_wol[DIMN*DIMN];
__device__ float g_kp[NTOK*DIMN];
__device__ float g_qp[NTOK*DIMN];
__device__ bf g_kph[NTOK*DIMN], g_kpl[NTOK*DIMN];
__device__ bf g_qph[NTOK*DIMN], g_qpl[NTOK*DIMN];
__device__ bf g_vph[NTOK*DIMN], g_vpl[NTOK*DIMN];
__device__ float g_h1[BC*HIDN];
__device__ bf g_a1h[BC*HIDN], g_a1l[BC*HIDN];
__device__ bf g_d2h[BC*DIMN], g_d2l[BC*DIMN];
__device__ bf g_d1h[BC*HIDN], g_d1l[BC*HIDN];
__device__ bf g_aqh[BC*HIDN], g_aql[BC*HIDN];
__device__ bf g_yh[NTOK*DIMN], g_yl[NTOK*DIMN];
__device__ float g_w1f[2][HIDN*DIMN];
__device__ bf    g_w1h[2][HIDN*DIMN], g_w1l[2][HIDN*DIMN];
__device__ float g_w2f[2][DIMN*HIDN];
__device__ bf    g_w2h[2][DIMN*HIDN], g_w2l[2][DIMN*HIDN];
__device__ float g_m1[HIDN*DIMN];
__device__ float g_m2[DIMN*HIDN];
__device__ float g_gate_tok[NTOK*3];
__device__ float g_gates[NCH*3];

// ---------------- math helpers ----------------
__device__ __forceinline__ float sigf(float x){ return 1.0f/(1.0f+expf(-x)); }
__device__ __forceinline__ float siluf(float x){ return x*sigf(x); }
__device__ __forceinline__ float siluderivf(float x){ float s=sigf(x); return s*(1.0f + x*(1.0f-s)); }
__device__ __forceinline__ float clip1f(float x){ return fminf(fmaxf(x,-1.0f),1.0f); }
__device__ __forceinline__ void store_hl(bf* H, bf* L, size_t idx, float v){
    bf h = __float2bfloat16_rn(v);
    H[idx] = h;
    L[idx] = __float2bfloat16_rn(v - __bfloat162float(h));
}

// ---------------- mma / ldmatrix / cp.async primitives ----------------
__device__ __forceinline__ void mma_bf16(float* d, const unsigned* a, const unsigned* b){
    asm volatile(
        "mma.sync.aligned.m16n8k16.row.col.f32.bf16.bf16.f32 "
        "{%0,%1,%2,%3}, {%4,%5,%6,%7}, {%8,%9}, {%0,%1,%2,%3};\n"
        : "+f"(d[0]), "+f"(d[1]), "+f"(d[2]), "+f"(d[3])
        : "r"(a[0]), "r"(a[1]), "r"(a[2]), "r"(a[3]), "r"(b[0]), "r"(b[1]));
}
__device__ __forceinline__ void ldsm4(unsigned* r, const bf* p){
    unsigned a = (unsigned)__cvta_generic_to_shared(p);
    asm volatile("ldmatrix.sync.aligned.m8n8.x4.shared.b16 {%0,%1,%2,%3}, [%4];\n"
        : "=r"(r[0]), "=r"(r[1]), "=r"(r[2]), "=r"(r[3]) : "r"(a));
}
__device__ __forceinline__ void cpa16(bf* s, const bf* g){
    unsigned sa = (unsigned)__cvta_generic_to_shared(s);
    asm volatile("cp.async.cg.shared.global [%0], [%1], 16;\n" :: "r"(sa), "l"(g));
}
__device__ __forceinline__ void cp_commit(){ asm volatile("cp.async.commit_group;\n"); }
template<int N> __device__ __forceinline__ void cp_wait(){ asm volatile("cp.async.wait_group %0;\n" :: "n"(N)); }

// ---------------- register-staged loader (KM=false transpose path) ----------------
template<int R, bool KM, int KC, int KS>
struct Loader {
    static constexpr int CH = (R*KC)/(128*8);
    uint4 vh[CH], vl[CH];
    __device__ __forceinline__ void fetch(const bf* __restrict__ Ph, const bf* __restrict__ Pl,
                                          int ld, int r0, int k0, int tid){
        #pragma unroll
        for (int c = 0; c < CH; ++c){
            int id = tid + c*128;
            if constexpr (KM){
                int r = id/(KC/8), kq = (id%(KC/8))*8;
                size_t off = (size_t)(r0+r)*ld + k0 + kq;
                vh[c] = *(const uint4*)(Ph + off);
                vl[c] = *(const uint4*)(Pl + off);
            } else {
                int k = id/(R/8), rq = (id%(R/8))*8;
                size_t off = (size_t)(k0+k)*ld + r0 + rq;
                vh[c] = *(const uint4*)(Ph + off);
                vl[c] = *(const uint4*)(Pl + off);
            }
        }
    }
    __device__ __forceinline__ void store(bf* Sh, bf* Sl, int tid){
        #pragma unroll
        for (int c = 0; c < CH; ++c){
            int id = tid + c*128;
            if constexpr (KM){
                int r = id/(KC/8), kq = (id%(KC/8))*8;
                *(uint4*)(Sh + r*KS + kq) = vh[c];
                *(uint4*)(Sl + r*KS + kq) = vl[c];
            } else {
                int k = id/(R/8), rq = (id%(R/8))*8;
                const bf* ph = (const bf*)&vh[c];
                const bf* pl = (const bf*)&vl[c];
                #pragma unroll
                for (int j = 0; j < 8; ++j){
                    Sh[(rq+j)*KS + k] = ph[j];
                    Sl[(rq+j)*KS + k] = pl[j];
                }
            }
        }
    }
};

// ---------------- GEMM core: C[M,N] = sum_k A(m,k)*B(n,k) ----------------
// EP: 0 C=acc | 1 C=acc,Ch/Cl=silu | 2 Ch/Cl=scale*clip(acc-(x0h+x0l)) | 3 Ch/Cl=acc*silu'(f0)
//     4 weight update | 5 Ch/Cl=silu | 6 Ch/Cl=acc natural-layout | 7 C=silu perm | 8 Ch/Cl=silu perm
template<int BM,int BN,bool AKM,bool BKM,int EP>
__device__ __forceinline__ void mgemm_core(
    char* dsm,
    const bf* __restrict__ Ah, const bf* __restrict__ Al, int lda,
    const bf* __restrict__ Bh, const bf* __restrict__ Bl, int ldb,
    float* __restrict__ C, bf* __restrict__ Ch, bf* __restrict__ Cl, int ldc,
    int K,
    const float* __restrict__ f0,
    const bf* __restrict__ x0h, const bf* __restrict__ x0l,
    float* __restrict__ f1,
    const float* __restrict__ gates,
    float scale, int base, int m0, int n0)
{
    constexpr int KC = 32;
    constexpr int KS = 40;
    constexpr int NI = (BM == 64) ? 4 : 2;
    constexpr int NJ = NI/2;
    constexpr int ASZ = BM*KS, BSZ = BN*KS;
    constexpr int STRIDE = 2*ASZ + 2*BSZ;

    const int tid  = threadIdx.x;
    const int lane = tid & 31;
    const int wid  = tid >> 5;
    const int g    = lane >> 2;
    const int tg   = lane & 3;
    const int wm = (BM == 64) ? (wid >> 1) * 32 : 0;
    const int wn = (BM == 64) ? (wid & 1) * 32 : wid * 16;
    const int aoff = (lane & 15)*KS + (lane >> 4)*8;
    const int boff = ((lane & 7) + ((lane >> 4) & 1)*8)*KS + ((lane >> 3) & 1)*8;

    bf* base_s = (bf*)dsm;

    float accm[2][NI][4] = {};
    float accc[2][NI][4] = {};

    auto compute_tile = [&](const bf* Ahs, const bf* Als, const bf* Bhs, const bf* Bls){
        #pragma unroll
        for (int kt = 0; kt < KC; kt += 16) {
            unsigned ah[2][4], al_[2][4], b2h[NJ][4], b2l[NJ][4];
            #pragma unroll
            for (int mi = 0; mi < 2; ++mi) {
                ldsm4(ah[mi],  Ahs + (wm + mi*16)*KS + kt + aoff);
                ldsm4(al_[mi], Als + (wm + mi*16)*KS + kt + aoff);
            }
            #pragma unroll
            for (int nj = 0; nj < NJ; ++nj) {
                ldsm4(b2h[nj], Bhs + (wn + nj*16)*KS + kt + boff);
                ldsm4(b2l[nj], Bls + (wn + nj*16)*KS + kt + boff);
            }
            #pragma unroll
            for (int mi = 0; mi < 2; ++mi)
                #pragma unroll
                for (int nj = 0; nj < NJ; ++nj) {
                    mma_bf16(accm[mi][nj*2+0], ah[mi],  b2h[nj]+0);
                    mma_bf16(accm[mi][nj*2+1], ah[mi],  b2h[nj]+2);
                    mma_bf16(accc[mi][nj*2+0], ah[mi],  b2l[nj]+0);
                    mma_bf16(accc[mi][nj*2+1], ah[mi],  b2l[nj]+2);
                    mma_bf16(accc[mi][nj*2+0], al_[mi], b2h[nj]+0);
                    mma_bf16(accc[mi][nj*2+1], al_[mi], b2h[nj]+2);
                }
        }
    };

    if constexpr (AKM && BKM) {
        // ---- 4-stage cp.async pipeline ----
        constexpr int STG = 4;
        const int KT = K / KC;
        auto issue = [&](int s, int k0){
            bf* dAh = base_s + s*STRIDE; bf* dAl = dAh + ASZ;
            bf* dBh = dAl + ASZ;         bf* dBl = dBh + BSZ;
            #pragma unroll
            for (int c2 = 0; c2 < (BM*4)/128; ++c2){
                int id = tid + c2*128; int r = id >> 2, kq = (id & 3)*8;
                size_t off = (size_t)(m0+r)*lda + k0 + kq;
                cpa16(dAh + r*KS + kq, Ah + off);
                cpa16(dAl + r*KS + kq, Al + off);
            }
            #pragma unroll
            for (int c2 = 0; c2 < (BN*4)/128; ++c2){
                int id = tid + c2*128; int r = id >> 2, kq = (id & 3)*8;
                size_t off = (size_t)(n0+r)*ldb + k0 + kq;
                cpa16(dBh + r*KS + kq, Bh + off);
                cpa16(dBl + r*KS + kq, Bl + off);
            }
            cp_commit();
        };
        int fetch = 0;
        for (; fetch < STG-1 && fetch < KT; ++fetch) issue(fetch, fetch*KC);
        for (int c = 0; c < KT; ++c){
            int nrem = fetch - 1 - c;
            if (nrem >= 2) cp_wait<2>(); else if (nrem == 1) cp_wait<1>(); else cp_wait<0>();
            __syncthreads();
            if (fetch < KT){ issue(fetch % STG, fetch*KC); ++fetch; }
            int s = c % STG;
            bf* pAh = base_s + s*STRIDE; bf* pAl = pAh + ASZ;
            bf* pBh = pAl + ASZ;         bf* pBl = pBh + BSZ;
            compute_tile(pAh, pAl, pBh, pBl);
        }
    } else {
        // ---- register-staged 2-buffer path (handles transpose loads) ----
        Loader<BM,AKM,KC,KS> la;
        Loader<BN,BKM,KC,KS> lb;
        bf* A0[2]; bf* A1[2]; bf* B0[2]; bf* B1[2];
        #pragma unroll
        for (int b = 0; b < 2; ++b){
            bf* p = base_s + b*STRIDE;
            A0[b] = p; A1[b] = p + ASZ; B0[b] = p + 2*ASZ; B1[b] = p + 2*ASZ + BSZ;
        }
        la.fetch(Ah, Al, lda, m0, 0, tid);
        lb.fetch(Bh, Bl, ldb, n0, 0, tid);
        la.store(A0[0], A1[0], tid);
        lb.store(B0[0], B1[0], tid);
        __syncthreads();
        int cur = 0;
        for (int k0 = 0; k0 < K; k0 += KC) {
            bool more = (k0 + KC) < K;
            if (more) {
                la.fetch(Ah, Al, lda, m0, k0 + KC, tid);
                lb.fetch(Bh, Bl, ldb, n0, k0 + KC, tid);
            }
            compute_tile(A0[cur], A1[cur], B0[cur], B1[cur]);
            if (more) {
                la.store(A0[cur^1], A1[cur^1], tid);
                lb.store(B0[cur^1], B1[cur^1], tid);
                __syncthreads();
                cur ^= 1;
            }
        }
    }

    // ---- epilogue ----
    float lrg = 0.f, alg = 0.f, etg = 0.f;
    if constexpr (EP == 4) { lrg = gates[0]; alg = gates[1]; etg = gates[2]; }

    #pragma unroll
    for (int mi = 0; mi < 2; ++mi)
    #pragma unroll
    for (int rr = 0; rr < 2; ++rr) {
        int m = m0 + wm + mi*16 + rr*8 + g;
        size_t crow;
        if constexpr (EP == 6) {
            int b = m >> 6, ci = m & 63;
            crow = (size_t)(b*SS + base + ci) * ldc;
        } else if constexpr (EP == 7 || EP == 8) {
            int b = m >> 11, s = m & (SS-1);
            crow = (size_t)((s >> 6)*BC + b*CHK + (s & 63)) * ldc;
        } else {
            crow = (size_t)m * ldc;
        }
        size_t srow = (size_t)m * ldc;
        #pragma unroll
        for (int ni = 0; ni < NI; ++ni) {
            int n = n0 + wn + ni*8 + tg*2;
            #pragma unroll
            for (int cc = 0; cc < 2; ++cc) {
                float v = accm[mi][ni][rr*2 + cc] + accc[mi][ni][rr*2 + cc];
                size_t idx  = crow + n + cc;
                size_t sidx = srow + n + cc;
                if constexpr (EP == 0) C[idx] = v;
                else if constexpr (EP == 1) { C[idx] = v; store_hl(Ch, Cl, idx, siluf(v)); }
                else if constexpr (EP == 2) {
                    float vv = __bfloat162float(x0h[sidx]) + __bfloat162float(x0l[sidx]);
                    store_hl(Ch, Cl, idx, scale * clip1f(v - vv));
                }
                else if constexpr (EP == 3) store_hl(Ch, Cl, idx, v * siluderivf(f0[sidx]));
                else if constexpr (EP == 4) {
                    float gg = clip1f(v);
                    float mn = etg * f1[idx] - lrg * gg;
                    f1[idx] = mn;
                    float w = (1.0f - alg) * f0[idx] + mn;
                    C[idx] = w;
                    store_hl(Ch, Cl, idx, w);
                }
                else if constexpr (EP == 5) store_hl(Ch, Cl, idx, siluf(v));
                else if constexpr (EP == 6) store_hl(Ch, Cl, idx, v);
                else if constexpr (EP == 7) C[idx] = siluf(v);
                else if constexpr (EP == 8) store_hl(Ch, Cl, idx, siluf(v));
            }
        }
    }
}

template<int BM,int BN,bool AKM,bool BKM,int EP>
__global__ __launch_bounds__(128,2)
void mgemm_k(const bf* __restrict__ Ah, const bf* __restrict__ Al, int lda,
             const bf* __restrict__ Bh, const bf* __restrict__ Bl, int ldb,
             float* __restrict__ C, bf* __restrict__ Ch, bf* __restrict__ Cl, int ldc,
             int K,
             const float* __restrict__ f0,
             const bf* __restrict__ x0h, const bf* __restrict__ x0l,
             float* __restrict__ f1,
             const float* __restrict__ gates, float scale, int base)
{
    extern __shared__ __align__(16) char dsm[];
    mgemm_core<BM,BN,AKM,BKM,EP>(dsm, Ah,Al,lda, Bh,Bl,ldb, C,Ch,Cl,ldc, K,
                                 f0,x0h,x0l,f1, gates, scale, base,
                                 blockIdx.y*BM, blockIdx.x*BN);
}

// fused weight updates (w2 grad + w1 grad), both EP4, 64x64 tiles, K=BC
__global__ __launch_bounds__(128,2)
void wupd_k(const bf* __restrict__ kth, const bf* __restrict__ ktl,
            float* __restrict__ w2n, bf* __restrict__ w2nh, bf* __restrict__ w2nl,
            const float* __restrict__ w2o,
            float* __restrict__ w1n, bf* __restrict__ w1nh, bf* __restrict__ w1nl,
            const float* __restrict__ w1o,
            const float* __restrict__ gates)
{
    extern __shared__ __align__(16) char dsm[];
    int bx = blockIdx.x;
    constexpr int T2 = (HIDN/64)*(DIMN/64);
    if (bx < T2) {
        int nt = bx % (HIDN/64), mt = bx / (HIDN/64);
        mgemm_core<64,64,false,false,4>(dsm, g_d2h,g_d2l,DIMN, g_a1h,g_a1l,HIDN,
                                        w2n,w2nh,w2nl,HIDN, BC,
                                        w2o,nullptr,nullptr,g_m2, gates, 0.f, 0,
                                        mt*64, nt*64);
    } else {
        int i = bx - T2;
        int nt = i % (DIMN/64), mt = i / (DIMN/64);
        mgemm_core<64,64,false,false,4>(dsm, g_d1h,g_d1l,HIDN, kth,ktl,DIMN,
                                        w1n,w1nh,w1nl,DIMN, BC,
                                        w1o,nullptr,nullptr,g_m1, gates, 0.f, 0,
                                        mt*64, nt*64);
    }
}

// ---------------- fused preamble: all splits + momentum zeroing, ONE launch ----------------
__device__ __forceinline__ void split_body(const float* __restrict__ s, bf* __restrict__ h,
                                           bf* __restrict__ l, int i)
{
    float4 v = *(const float4*)(s + i);
    float f[4] = {v.x, v.y, v.z, v.w};
    bf hv[4], lv[4];
    #pragma unroll
    for (int j = 0; j < 4; ++j) {
        hv[j] = __float2bfloat16_rn(f[j]);
        lv[j] = __float2bfloat16_rn(f[j] - __bfloat162float(hv[j]));
    }
    *(uint2*)(h + i) = *(uint2*)hv;
    *(uint2*)(l + i) = *(uint2*)lv;
}
// segments (blocks of 1024 elems): x 8192 | wk 1024 | wv 1024 | wq 1024 | wout 1024
// | w1 2048 | w2 2048 | zero m1 2048 | zero m2 2048   -> 20480 blocks total
__global__ void prep_k(const float* __restrict__ x,  const float* __restrict__ Wk,
                       const float* __restrict__ Wv, const float* __restrict__ Wq,
                       const float* __restrict__ Wo, const float* __restrict__ W1,
                       const float* __restrict__ W2)
{
    int b = blockIdx.x;
    const float* s; bf *h, *l; float* z = nullptr;
    if      (b <  8192){            s=x;  h=g_xh;      l=g_xl; }
    else if (b <  9216){ b-= 8192;  s=Wk; h=g_wkh;     l=g_wkl; }
    else if (b < 10240){ b-= 9216;  s=Wv; h=g_wvh;     l=g_wvl; }
    else if (b < 11264){ b-=10240;  s=Wq; h=g_wqh;     l=g_wql; }
    else if (b < 12288){ b-=11264;  s=Wo; h=g_woh;     l=g_wol; }
    else if (b < 14336){ b-=12288;  s=W1; h=g_w1h[1];  l=g_w1l[1]; }
    else if (b < 16384){ b-=14336;  s=W2; h=g_w2h[1];  l=g_w2l[1]; }
    else if (b < 18432){ b-=16384;  z=g_m1; s=nullptr; h=nullptr; l=nullptr; }
    else               { b-=18432;  z=g_m2; s=nullptr; h=nullptr; l=nullptr; }
    int i = (b*256 + threadIdx.x)*4;
    if (z){ *(float4*)(z + i) = make_float4(0.f,0.f,0.f,0.f); return; }
    split_body(s, h, l, i);
}

// ---------------- fused 3-way projection (k,q,v) ----------------
__global__ __launch_bounds__(128,2)
void proj_k()
{
    extern __shared__ __align__(16) char dsm[];
    int m0 = blockIdx.y*64, n0 = blockIdx.x*64;
    if (blockIdx.z == 0)
        mgemm_core<64,64,true,true,7>(dsm, g_xh,g_xl,DIMN, g_wkh,g_wkl,DIMN,
            g_kp,nullptr,nullptr,DIMN, DIMN, nullptr,nullptr,nullptr,nullptr,
            nullptr,0.f,0, m0, n0);
    else if (blockIdx.z == 1)
        mgemm_core<64,64,true,true,7>(dsm, g_xh,g_xl,DIMN, g_wqh,g_wql,DIMN,
            g_qp,nullptr,nullptr,DIMN, DIMN, nullptr,nullptr,nullptr,nullptr,
            nullptr,0.f,0, m0, n0);
    else
        mgemm_core<64,64,true,true,8>(dsm, g_xh,g_xl,DIMN, g_wvh,g_wvl,DIMN,
            nullptr,g_vph,g_vpl,DIMN, DIMN, nullptr,nullptr,nullptr,nullptr,
            nullptr,0.f,0, m0, n0);
}

// ---------------- fused l2 normalize (k then q), fp32 row -> hi/lo bf16 ----------------
__global__ void l2norm2_k()
{
    int bid = blockIdx.x;
    const float* src; bf *h, *l;
    if (bid < NTOK){ src = g_kp; h = g_kph; l = g_kpl; }
    else           { bid -= NTOK; src = g_qp; h = g_qph; l = g_qpl; }
    const float* r = src + (size_t)bid * DIMN;
    int t = threadIdx.x;
    float4 v = *(const float4*)(r + t*4);
    float ss = v.x*v.x + v.y*v.y + v.z*v.z + v.w*v.w;
    __shared__ float red[256];
    red[t] = ss; __syncthreads();
    for (int o = 128; o > 0; o >>= 1) { if (t < o) red[t] += red[t+o]; __syncthreads(); }
    float inv = rsqrtf(red[0] + EPSN);
    float f[4] = {v.x*inv, v.y*inv, v.z*inv, v.w*inv};
    bf hv[4], lv[4];
    #pragma unroll
    for (int j = 0; j < 4; ++j) {
        hv[j] = __float2bfloat16_rn(f[j]);
        lv[j] = __float2bfloat16_rn(f[j] - __bfloat162float(hv[j]));
    }
    size_t o4 = (size_t)bid * DIMN + t*4;
    *(uint2*)(h + o4) = *(uint2*)hv;
    *(uint2*)(l + o4) = *(uint2*)lv;
}

// ---------------- per-token gate dots ----------------
__global__ void gate_tok_k(const float* __restrict__ x,
                           const float* __restrict__ wlr,  const float* __restrict__ blr,
                           const float* __restrict__ wdec, const float* __restrict__ bdec,
                           const float* __restrict__ wmom, const float* __restrict__ bmom)
{
    int tok = blockIdx.x;
    int t = threadIdx.x;
    const float* xr = x + (size_t)tok * DIMN;
    float s0 = 0.f, s1 = 0.f, s2 = 0.f;
    for (int i = t; i < DIMN; i += 256) {
        float xi = xr[i];
        s0 += xi * wlr[i]; s1 += xi * wdec[i]; s2 += xi * wmom[i];
    }
    __shared__ float r0[256], r1[256], r2[256];
    r0[t] = s0; r1[t] = s1; r2[t] = s2; __syncthreads();
    for (int o = 128; o > 0; o >>= 1) {
        if (t < o) { r0[t] += r0[t+o]; r1[t] += r1[t+o]; r2[t] += r2[t+o]; }
        __syncthreads();
    }
    if (t == 0) {
        g_gate_tok[tok*3+0] = sigf(r0[0] + blr[0]);
        g_gate_tok[tok*3+1] = sigf(r1[0] + bdec[0]);
        g_gate_tok[tok*3+2] = sigf(r2[0] + bmom[0]);
    }
}

// ---------------- per-chunk gate means ----------------
__global__ void gate_chunk_k()
{
    int ch = blockIdx.x;
    int t = threadIdx.x;
    int b = t >> 6, ci = t & 63;
    int tok = b*SS + ch*CHK + ci;
    __shared__ float r0[256], r1[256], r2[256];
    r0[t] = g_gate_tok[tok*3+0];
    r1[t] = g_gate_tok[tok*3+1];
    r2[t] = g_gate_tok[tok*3+2];
    __syncthreads();
    for (int o = 128; o > 0; o >>= 1) {
        if (t < o) { r0[t] += r0[t+o]; r1[t] += r1[t+o]; r2[t] += r2[t+o]; }
        __syncthreads();
    }
    if (t == 0) {
        g_gates[ch*3+0] = r0[0] * (1.0f/BC);
        g_gates[ch*3+1] = r1[0] * (1.0f/BC);
        g_gates[ch*3+2] = r2[0] * (1.0f/BC);
    }
}

// smem sizes per config
#define SM_A64 (4*(2*64+2*64)*40*2)   // 81920
#define SM_A32 (4*(2*32+2*64)*40*2)   // 61440
#define SM_R32 (2*(2*32+2*64)*40*2)   // 30720
#define SM_R64 (2*(2*64+2*64)*40*2)   // 40960

// ---------------- host orchestration ----------------
extern "C" void kernel_launch(void* const* d_in, const int* in_sizes, int n_in,
                              void* d_out, int out_size)
{
    const float* x    = (const float*)d_in[0];
    const float* Wk   = (const float*)d_in[1];
    const float* Wv   = (const float*)d_in[2];
    const float* Wq   = (const float*)d_in[3];
    const float* Wout = (const float*)d_in[4];
    const float* W1   = (const float*)d_in[5];
    const float* W2   = (const float*)d_in[6];
    const float* Wlr  = (const float*)d_in[7];
    const float* blr  = (const float*)d_in[8];
    const float* Wdec = (const float*)d_in[9];
    const float* bdec = (const float*)d_in[10];
    const float* Wmom = (const float*)d_in[11];
    const float* bmom = (const float*)d_in[12];
    float* out = (float*)d_out;

    static cudaStream_t s2 = nullptr;
    static cudaEvent_t evA = nullptr, evB0 = nullptr, evB1 = nullptr;
    if (!s2) {
        cudaStreamCreateWithFlags(&s2, cudaStreamNonBlocking);
        cudaEventCreateWithFlags(&evA,  cudaEventDisableTiming);
        cudaEventCreateWithFlags(&evB0, cudaEventDisableTiming);
        cudaEventCreateWithFlags(&evB1, cudaEventDisableTiming);
        cudaFuncSetAttribute(proj_k, cudaFuncAttributeMaxDynamicSharedMemorySize, SM_A64);
        cudaFuncSetAttribute(mgemm_k<64,64,true,true,0>, cudaFuncAttributeMaxDynamicSharedMemorySize, SM_A64);
        cudaFuncSetAttribute(mgemm_k<32,64,true,true,1>, cudaFuncAttributeMaxDynamicSharedMemorySize, SM_A32);
        cudaFuncSetAttribute(mgemm_k<32,64,true,true,2>, cudaFuncAttributeMaxDynamicSharedMemorySize, SM_A32);
        cudaFuncSetAttribute(mgemm_k<32,64,true,true,5>, cudaFuncAttributeMaxDynamicSharedMemorySize, SM_A32);
        cudaFuncSetAttribute(mgemm_k<32,64,true,true,6>, cudaFuncAttributeMaxDynamicSharedMemorySize, SM_A32);
        cudaFuncSetAttribute(mgemm_k<32,64,true,false,3>, cudaFuncAttributeMaxDynamicSharedMemorySize, SM_R32);
        cudaFuncSetAttribute(wupd_k, cudaFuncAttributeMaxDynamicSharedMemorySize, SM_R64);
    }

    bf *kph,*kpl,*qph,*qpl,*vph,*vpl;
    bf *a1h,*a1l,*d2h,*d2l,*d1h,*d1l,*aqh,*aql,*yh,*yl,*woh,*wol;
    float *h1,*gch;
    float *w1f0,*w1f1,*w2f0,*w2f1;
    bf *w1h0,*w1h1,*w1l0,*w1l1,*w2h0,*w2h1,*w2l0,*w2l1;

    cudaGetSymbolAddress((void**)&woh,g_woh);  cudaGetSymbolAddress((void**)&wol,g_wol);
    cudaGetSymbolAddress((void**)&kph,g_kph);  cudaGetSymbolAddress((void**)&kpl,g_kpl);
    cudaGetSymbolAddress((void**)&qph,g_qph);  cudaGetSymbolAddress((void**)&qpl,g_qpl);
    cudaGetSymbolAddress((void**)&vph,g_vph);  cudaGetSymbolAddress((void**)&vpl,g_vpl);
    cudaGetSymbolAddress((void**)&h1, g_h1);
    cudaGetSymbolAddress((void**)&a1h,g_a1h);  cudaGetSymbolAddress((void**)&a1l,g_a1l);
    cudaGetSymbolAddress((void**)&d2h,g_d2h);  cudaGetSymbolAddress((void**)&d2l,g_d2l);
    cudaGetSymbolAddress((void**)&d1h,g_d1h);  cudaGetSymbolAddress((void**)&d1l,g_d1l);
    cudaGetSymbolAddress((void**)&aqh,g_aqh);  cudaGetSymbolAddress((void**)&aql,g_aql);
    cudaGetSymbolAddress((void**)&yh, g_yh);   cudaGetSymbolAddress((void**)&yl, g_yl);
    cudaGetSymbolAddress((void**)&gch,g_gates);
    { void* p;
      cudaGetSymbolAddress(&p, g_w1f); w1f0=(float*)p; w1f1=w1f0+HIDN*DIMN;
      cudaGetSymbolAddress(&p, g_w1h); w1h0=(bf*)p;    w1h1=w1h0+HIDN*DIMN;
      cudaGetSymbolAddress(&p, g_w1l); w1l0=(bf*)p;    w1l1=w1l0+HIDN*DIMN;
      cudaGetSymbolAddress(&p, g_w2f); w2f0=(float*)p; w2f1=w2f0+DIMN*HIDN;
      cudaGetSymbolAddress(&p, g_w2h); w2h0=(bf*)p;    w2h1=w2h0+DIMN*HIDN;
      cudaGetSymbolAddress(&p, g_w2l); w2l0=(bf*)p;    w2l1=w2l0+DIMN*HIDN;
    }

    // launch 0: fused splits + momentum zeroing
    prep_k<<<20480, 256>>>(x, Wk, Wv, Wq, Wout, W1, W2);
    // launches 1,2: gates
    gate_tok_k<<<NTOK, 256>>>(x, Wlr, blr, Wdec, bdec, Wmom, bmom);
    gate_chunk_k<<<NCH, 256>>>();
    // launch 3: fused projections (k,q,v)
    proj_k<<<dim3(DIMN/64, NTOK/64, 3),128,SM_A64>>>();
    // launch 4: fused l2norm (k+q)
    l2norm2_k<<<2*NTOK,256>>>();
    // launch 5 = chunk-0 step-1 (ncu capture target)

    for (int ch = 0; ch < NCH; ++ch) {
        size_t co = (size_t)ch*BC*DIMN;
        const bf *kth = kph+co, *ktl = kpl+co;
        const bf *qth = qph+co, *qtl = qpl+co;
        const bf *vth = vph+co, *vtl = vpl+co;
        int wi = ch & 1;
        int ri = 1 - wi;
        const float* w1o = (ch == 0) ? W1 : (ri ? w1f1 : w1f0);
        const float* w2o = (ch == 0) ? W2 : (ri ? w2f1 : w2f0);
        const bf *w1rh = ri ? w1h1 : w1h0, *w1rl = ri ? w1l1 : w1l0;
        const bf *w2rh = ri ? w2h1 : w2h0, *w2rl = ri ? w2l1 : w2l0;
        float* w1n = wi ? w1f1 : w1f0;
        float* w2n = wi ? w2f1 : w2f0;
        bf *w1nh = wi ? w1h1 : w1h0, *w1nl = wi ? w1l1 : w1l0;
        bf *w2nh = wi ? w2h1 : w2h0, *w2nl = wi ? w2l1 : w2l0;
        const float* gp3 = gch + ch*3;

        // forward + grads on stream 0
        mgemm_k<32,64,true,true,1><<<dim3(HIDN/64, BC/32),128,SM_A32>>>(
            kth,ktl,DIMN, w1rh,w1rl,DIMN, h1,a1h,a1l,HIDN, DIMN,
            nullptr,nullptr,nullptr,nullptr, nullptr,0.f,0);
        mgemm_k<32,64,true,true,2><<<dim3(DIMN/64, BC/32),128,SM_A32>>>(
            a1h,a1l,HIDN, w2rh,w2rl,HIDN, nullptr,d2h,d2l,DIMN, HIDN,
            nullptr,vth,vtl,nullptr, nullptr,SCALE_CONST,0);
        mgemm_k<32,64,true,false,3><<<dim3(HIDN/64, BC/32),128,SM_R32>>>(
            d2h,d2l,DIMN, w2rh,w2rl,HIDN, nullptr,d1h,d1l,HIDN, DIMN,
            h1,nullptr,nullptr,nullptr, nullptr,0.f,0);
        // wupd(ch) rewrites weight slot (ch&1): wait until retrieval of ch-2 (same slot) finished
        if (ch >= 2) cudaStreamWaitEvent(0, (ch & 1) ? evB1 : evB0, 0);
        wupd_k<<<(HIDN/64)*(DIMN/64)*2,128,SM_R64>>>(
            kth,ktl, w2n,w2nh,w2nl, w2o, w1n,w1nh,w1nl, w1o, gp3);
        // retrieval on stream 2, overlapped with next chunk's forward
        cudaEventRecord(evA, 0);
        cudaStreamWaitEvent(s2, evA, 0);
        mgemm_k<32,64,true,true,5><<<dim3(HIDN/64, BC/32),128,SM_A32,s2>>>(
            qth,qtl,DIMN, w1nh,w1nl,DIMN, nullptr,aqh,aql,HIDN, DIMN,
            nullptr,nullptr,nullptr,nullptr, nullptr,0.f,0);
        mgemm_k<32,64,true,true,6><<<dim3(DIMN/64, BC/32),128,SM_A32,s2>>>(
            aqh,aql,HIDN, w2nh,w2nl,HIDN, nullptr,yh,yl,DIMN, HIDN,
            nullptr,nullptr,nullptr,nullptr, nullptr,0.f,ch*CHK);
        cudaEventRecord((ch & 1) ? evB1 : evB0, s2);
    }

    // join retrieval stream, then output projection
    cudaStreamWaitEvent(0, ((NCH-1) & 1) ? evB1 : evB0, 0);
    mgemm_k<64,64,true,true,0><<<dim3(DIMN/64, NTOK/64),128,SM_A64>>>(
        yh,yl,DIMN, woh,wol,DIMN, out,nullptr,nullptr,DIMN, DIMN,
        nullptr,nullptr,nullptr,nullptr, nullptr,0.f,0);
}

// round 16
// speedup vs baseline: 1.2119x; 1.0100x over previous
#include <cuda_runtime.h>
#include <cuda_bf16.h>
#include <math.h>

// ---------------- problem constants ----------------
#define DIMN 1024
#define HIDN 2048
#define BB   4
#define SS   2048
#define CHK  64
#define NCH  32        // SS/CHK
#define BC   256       // BB*CHK
#define NTOK 8192      // BB*SS
#define EPSN 1e-8f
#define SCALE_CONST (2.0f/(BB*CHK*DIMN))

using bf = __nv_bfloat16;

// ---------------- device scratch (no runtime allocs allowed) ----------------
__device__ bf g_xh[NTOK*DIMN],  g_xl[NTOK*DIMN];
__device__ bf g_wkh[DIMN*DIMN], g_wkl[DIMN*DIMN];
__device__ bf g_wvh[DIMN*DIMN], g_wvl[DIMN*DIMN];
__device__ bf g_wqh[DIMN*DIMN], g_wql[DIMN*DIMN];
__device__ bf g_woh[DIMN*DIMN], g_wol[DIMN*DIMN];
__device__ float g_kp[NTOK*DIMN];
__device__ float g_qp[NTOK*DIMN];
__device__ bf g_kph[NTOK*DIMN], g_kpl[NTOK*DIMN];
__device__ bf g_qph[NTOK*DIMN], g_qpl[NTOK*DIMN];
__device__ bf g_vph[NTOK*DIMN], g_vpl[NTOK*DIMN];
__device__ float g_h1[BC*HIDN];
__device__ bf g_a1h[BC*HIDN], g_a1l[BC*HIDN];
__device__ bf g_d2h[BC*DIMN], g_d2l[BC*DIMN];
__device__ bf g_d1h[BC*HIDN], g_d1l[BC*HIDN];
__device__ bf g_aqh[BC*HIDN], g_aql[BC*HIDN];
__device__ bf g_yh[NTOK*DIMN], g_yl[NTOK*DIMN];
__device__ float g_w1f[2][HIDN*DIMN];
__device__ bf    g_w1h[2][HIDN*DIMN], g_w1l[2][HIDN*DIMN];
__device__ float g_w2f[2][DIMN*HIDN];
__device__ bf    g_w2h[2][DIMN*HIDN], g_w2l[2][DIMN*HIDN];
__device__ float g_m1[HIDN*DIMN];
__device__ float g_m2[DIMN*HIDN];
__device__ float g_gate_tok[NTOK*3];
__device__ float g_gates[NCH*3];

// ---------------- math helpers ----------------
__device__ __forceinline__ float sigf(float x){ return 1.0f/(1.0f+expf(-x)); }
__device__ __forceinline__ float siluf(float x){ return x*sigf(x); }
__device__ __forceinline__ float siluderivf(float x){ float s=sigf(x); return s*(1.0f + x*(1.0f-s)); }
__device__ __forceinline__ float clip1f(float x){ return fminf(fmaxf(x,-1.0f),1.0f); }
__device__ __forceinline__ void store_hl(bf* H, bf* L, size_t idx, float v){
    bf h = __float2bfloat16_rn(v);
    H[idx] = h;
    L[idx] = __float2bfloat16_rn(v - __bfloat162float(h));
}

// ---------------- mma / ldmatrix / cp.async primitives ----------------
__device__ __forceinline__ void mma_bf16(float* d, const unsigned* a, const unsigned* b){
    asm volatile(
        "mma.sync.aligned.m16n8k16.row.col.f32.bf16.bf16.f32 "
        "{%0,%1,%2,%3}, {%4,%5,%6,%7}, {%8,%9}, {%0,%1,%2,%3};\n"
        : "+f"(d[0]), "+f"(d[1]), "+f"(d[2]), "+f"(d[3])
        : "r"(a[0]), "r"(a[1]), "r"(a[2]), "r"(a[3]), "r"(b[0]), "r"(b[1]));
}
__device__ __forceinline__ void ldsm4(unsigned* r, const bf* p){
    unsigned a = (unsigned)__cvta_generic_to_shared(p);
    asm volatile("ldmatrix.sync.aligned.m8n8.x4.shared.b16 {%0,%1,%2,%3}, [%4];\n"
        : "=r"(r[0]), "=r"(r[1]), "=r"(r[2]), "=r"(r[3]) : "r"(a));
}
__device__ __forceinline__ void cpa16(bf* s, const bf* g){
    unsigned sa = (unsigned)__cvta_generic_to_shared(s);
    asm volatile("cp.async.cg.shared.global [%0], [%1], 16;\n" :: "r"(sa), "l"(g));
}
__device__ __forceinline__ void cp_commit(){ asm volatile("cp.async.commit_group;\n"); }
template<int N> __device__ __forceinline__ void cp_wait(){ asm volatile("cp.async.wait_group %0;\n" :: "n"(N)); }

// ---------------- register-staged loader (KM=false transpose path) ----------------
template<int R, bool KM, int KC, int KS>
struct Loader {
    static constexpr int CH = (R*KC)/(128*8);
    uint4 vh[CH], vl[CH];
    __device__ __forceinline__ void fetch(const bf* __restrict__ Ph, const bf* __restrict__ Pl,
                                          int ld, int r0, int k0, int tid){
        #pragma unroll
        for (int c = 0; c < CH; ++c){
            int id = tid + c*128;
            if constexpr (KM){
                int r = id/(KC/8), kq = (id%(KC/8))*8;
                size_t off = (size_t)(r0+r)*ld + k0 + kq;
                vh[c] = *(const uint4*)(Ph + off);
                vl[c] = *(const uint4*)(Pl + off);
            } else {
                int k = id/(R/8), rq = (id%(R/8))*8;
                size_t off = (size_t)(k0+k)*ld + r0 + rq;
                vh[c] = *(const uint4*)(Ph + off);
                vl[c] = *(const uint4*)(Pl + off);
            }
        }
    }
    __device__ __forceinline__ void store(bf* Sh, bf* Sl, int tid){
        #pragma unroll
        for (int c = 0; c < CH; ++c){
            int id = tid + c*128;
            if constexpr (KM){
                int r = id/(KC/8), kq = (id%(KC/8))*8;
                *(uint4*)(Sh + r*KS + kq) = vh[c];
                *(uint4*)(Sl + r*KS + kq) = vl[c];
            } else {
                int k = id/(R/8), rq = (id%(R/8))*8;
                const bf* ph = (const bf*)&vh[c];
                const bf* pl = (const bf*)&vl[c];
                #pragma unroll
                for (int j = 0; j < 8; ++j){
                    Sh[(rq+j)*KS + k] = ph[j];
                    Sl[(rq+j)*KS + k] = pl[j];
                }
            }
        }
    }
};

// ---------------- GEMM core: C[M,N] = sum_k A(m,k)*B(n,k) ----------------
// EP: 0 C=acc | 1 C=acc,Ch/Cl=silu | 2 Ch/Cl=scale*clip(acc-(x0h+x0l)) | 3 Ch/Cl=acc*silu'(f0)
//     4 weight update | 5 Ch/Cl=silu | 6 Ch/Cl=acc natural-layout | 7 C=silu perm | 8 Ch/Cl=silu perm
template<int BM,int BN,bool AKM,bool BKM,int EP>
__device__ __forceinline__ void mgemm_core(
    char* dsm,
    const bf* __restrict__ Ah, const bf* __restrict__ Al, int lda,
    const bf* __restrict__ Bh, const bf* __restrict__ Bl, int ldb,
    float* __restrict__ C, bf* __restrict__ Ch, bf* __restrict__ Cl, int ldc,
    int K,
    const float* __restrict__ f0,
    const bf* __restrict__ x0h, const bf* __restrict__ x0l,
    float* __restrict__ f1,
    const float* __restrict__ gates,
    float scale, int base, int m0, int n0)
{
    constexpr int KC = 32;
    constexpr int KS = 40;
    constexpr int NI = (BM == 64) ? 4 : 2;
    constexpr int NJ = NI/2;
    constexpr int ASZ = BM*KS, BSZ = BN*KS;
    constexpr int STRIDE = 2*ASZ + 2*BSZ;

    const int tid  = threadIdx.x;
    const int lane = tid & 31;
    const int wid  = tid >> 5;
    const int g    = lane >> 2;
    const int tg   = lane & 3;
    const int wm = (BM == 64) ? (wid >> 1) * 32 : 0;
    const int wn = (BM == 64) ? (wid & 1) * 32 : wid * 16;
    const int aoff = (lane & 15)*KS + (lane >> 4)*8;
    const int boff = ((lane & 7) + ((lane >> 4) & 1)*8)*KS + ((lane >> 3) & 1)*8;

    bf* base_s = (bf*)dsm;

    float accm[2][NI][4] = {};
    float accc[2][NI][4] = {};

    auto compute_tile = [&](const bf* Ahs, const bf* Als, const bf* Bhs, const bf* Bls){
        #pragma unroll
        for (int kt = 0; kt < KC; kt += 16) {
            unsigned ah[2][4], al_[2][4], b2h[NJ][4], b2l[NJ][4];
            #pragma unroll
            for (int mi = 0; mi < 2; ++mi) {
                ldsm4(ah[mi],  Ahs + (wm + mi*16)*KS + kt + aoff);
                ldsm4(al_[mi], Als + (wm + mi*16)*KS + kt + aoff);
            }
            #pragma unroll
            for (int nj = 0; nj < NJ; ++nj) {
                ldsm4(b2h[nj], Bhs + (wn + nj*16)*KS + kt + boff);
                ldsm4(b2l[nj], Bls + (wn + nj*16)*KS + kt + boff);
            }
            #pragma unroll
            for (int mi = 0; mi < 2; ++mi)
                #pragma unroll
                for (int nj = 0; nj < NJ; ++nj) {
                    mma_bf16(accm[mi][nj*2+0], ah[mi],  b2h[nj]+0);
                    mma_bf16(accm[mi][nj*2+1], ah[mi],  b2h[nj]+2);
                    mma_bf16(accc[mi][nj*2+0], ah[mi],  b2l[nj]+0);
                    mma_bf16(accc[mi][nj*2+1], ah[mi],  b2l[nj]+2);
                    mma_bf16(accc[mi][nj*2+0], al_[mi], b2h[nj]+0);
                    mma_bf16(accc[mi][nj*2+1], al_[mi], b2h[nj]+2);
                }
        }
    };

    if constexpr (AKM && BKM) {
        // ---- 3-stage cp.async pipeline (3 blocks/SM residency) ----
        constexpr int STG = 3;
        const int KT = K / KC;
        auto issue = [&](int s, int k0){
            bf* dAh = base_s + s*STRIDE; bf* dAl = dAh + ASZ;
            bf* dBh = dAl + ASZ;         bf* dBl = dBh + BSZ;
            #pragma unroll
            for (int c2 = 0; c2 < (BM*4)/128; ++c2){
                int id = tid + c2*128; int r = id >> 2, kq = (id & 3)*8;
                size_t off = (size_t)(m0+r)*lda + k0 + kq;
                cpa16(dAh + r*KS + kq, Ah + off);
                cpa16(dAl + r*KS + kq, Al + off);
            }
            #pragma unroll
            for (int c2 = 0; c2 < (BN*4)/128; ++c2){
                int id = tid + c2*128; int r = id >> 2, kq = (id & 3)*8;
                size_t off = (size_t)(n0+r)*ldb + k0 + kq;
                cpa16(dBh + r*KS + kq, Bh + off);
                cpa16(dBl + r*KS + kq, Bl + off);
            }
            cp_commit();
        };
        int fetch = 0;
        for (; fetch < STG-1 && fetch < KT; ++fetch) issue(fetch, fetch*KC);
        for (int c = 0; c < KT; ++c){
            int nrem = fetch - 1 - c;
            if (nrem >= 1) cp_wait<1>(); else cp_wait<0>();
            __syncthreads();
            if (fetch < KT){ issue(fetch % STG, fetch*KC); ++fetch; }
            int s = c % STG;
            bf* pAh = base_s + s*STRIDE; bf* pAl = pAh + ASZ;
            bf* pBh = pAl + ASZ;         bf* pBl = pBh + BSZ;
            compute_tile(pAh, pAl, pBh, pBl);
        }
    } else {
        // ---- register-staged 2-buffer path (handles transpose loads) ----
        Loader<BM,AKM,KC,KS> la;
        Loader<BN,BKM,KC,KS> lb;
        bf* A0[2]; bf* A1[2]; bf* B0[2]; bf* B1[2];
        #pragma unroll
        for (int b = 0; b < 2; ++b){
            bf* p = base_s + b*STRIDE;
            A0[b] = p; A1[b] = p + ASZ; B0[b] = p + 2*ASZ; B1[b] = p + 2*ASZ + BSZ;
        }
        la.fetch(Ah, Al, lda, m0, 0, tid);
        lb.fetch(Bh, Bl, ldb, n0, 0, tid);
        la.store(A0[0], A1[0], tid);
        lb.store(B0[0], B1[0], tid);
        __syncthreads();
        int cur = 0;
        for (int k0 = 0; k0 < K; k0 += KC) {
            bool more = (k0 + KC) < K;
            if (more) {
                la.fetch(Ah, Al, lda, m0, k0 + KC, tid);
                lb.fetch(Bh, Bl, ldb, n0, k0 + KC, tid);
            }
            compute_tile(A0[cur], A1[cur], B0[cur], B1[cur]);
            if (more) {
                la.store(A0[cur^1], A1[cur^1], tid);
                lb.store(B0[cur^1], B1[cur^1], tid);
                __syncthreads();
                cur ^= 1;
            }
        }
    }

    // ---- epilogue ----
    float lrg = 0.f, alg = 0.f, etg = 0.f;
    if constexpr (EP == 4) { lrg = gates[0]; alg = gates[1]; etg = gates[2]; }

    #pragma unroll
    for (int mi = 0; mi < 2; ++mi)
    #pragma unroll
    for (int rr = 0; rr < 2; ++rr) {
        int m = m0 + wm + mi*16 + rr*8 + g;
        size_t crow;
        if constexpr (EP == 6) {
            int b = m >> 6, ci = m & 63;
            crow = (size_t)(b*SS + base + ci) * ldc;
        } else if constexpr (EP == 7 || EP == 8) {
            int b = m >> 11, s = m & (SS-1);
            crow = (size_t)((s >> 6)*BC + b*CHK + (s & 63)) * ldc;
        } else {
            crow = (size_t)m * ldc;
        }
        size_t srow = (size_t)m * ldc;
        #pragma unroll
        for (int ni = 0; ni < NI; ++ni) {
            int n = n0 + wn + ni*8 + tg*2;
            #pragma unroll
            for (int cc = 0; cc < 2; ++cc) {
                float v = accm[mi][ni][rr*2 + cc] + accc[mi][ni][rr*2 + cc];
                size_t idx  = crow + n + cc;
                size_t sidx = srow + n + cc;
                if constexpr (EP == 0) C[idx] = v;
                else if constexpr (EP == 1) { C[idx] = v; store_hl(Ch, Cl, idx, siluf(v)); }
                else if constexpr (EP == 2) {
                    float vv = __bfloat162float(x0h[sidx]) + __bfloat162float(x0l[sidx]);
                    store_hl(Ch, Cl, idx, scale * clip1f(v - vv));
                }
                else if constexpr (EP == 3) store_hl(Ch, Cl, idx, v * siluderivf(f0[sidx]));
                else if constexpr (EP == 4) {
                    float gg = clip1f(v);
                    float mn = etg * f1[idx] - lrg * gg;
                    f1[idx] = mn;
                    float w = (1.0f - alg) * f0[idx] + mn;
                    C[idx] = w;
                    store_hl(Ch, Cl, idx, w);
                }
                else if constexpr (EP == 5) store_hl(Ch, Cl, idx, siluf(v));
                else if constexpr (EP == 6) store_hl(Ch, Cl, idx, v);
                else if constexpr (EP == 7) C[idx] = siluf(v);
                else if constexpr (EP == 8) store_hl(Ch, Cl, idx, siluf(v));
            }
        }
    }
}

template<int BM,int BN,bool AKM,bool BKM,int EP>
__global__ __launch_bounds__(128,3)
void mgemm_k(const bf* __restrict__ Ah, const bf* __restrict__ Al, int lda,
             const bf* __restrict__ Bh, const bf* __restrict__ Bl, int ldb,
             float* __restrict__ C, bf* __restrict__ Ch, bf* __restrict__ Cl, int ldc,
             int K,
             const float* __restrict__ f0,
             const bf* __restrict__ x0h, const bf* __restrict__ x0l,
             float* __restrict__ f1,
             const float* __restrict__ gates, float scale, int base)
{
    extern __shared__ __align__(16) char dsm[];
    mgemm_core<BM,BN,AKM,BKM,EP>(dsm, Ah,Al,lda, Bh,Bl,ldb, C,Ch,Cl,ldc, K,
                                 f0,x0h,x0l,f1, gates, scale, base,
                                 blockIdx.y*BM, blockIdx.x*BN);
}

// fused weight updates (w2 grad + w1 grad), both EP4, 64x64 tiles, K=BC
__global__ __launch_bounds__(128,3)
void wupd_k(const bf* __restrict__ kth, const bf* __restrict__ ktl,
            float* __restrict__ w2n, bf* __restrict__ w2nh, bf* __restrict__ w2nl,
            const float* __restrict__ w2o,
            float* __restrict__ w1n, bf* __restrict__ w1nh, bf* __restrict__ w1nl,
            const float* __restrict__ w1o,
            const float* __restrict__ gates)
{
    extern __shared__ __align__(16) char dsm[];
    int bx = blockIdx.x;
    constexpr int T2 = (HIDN/64)*(DIMN/64);
    if (bx < T2) {
        int nt = bx % (HIDN/64), mt = bx / (HIDN/64);
        mgemm_core<64,64,false,false,4>(dsm, g_d2h,g_d2l,DIMN, g_a1h,g_a1l,HIDN,
                                        w2n,w2nh,w2nl,HIDN, BC,
                                        w2o,nullptr,nullptr,g_m2, gates, 0.f, 0,
                                        mt*64, nt*64);
    } else {
        int i = bx - T2;
        int nt = i % (DIMN/64), mt = i / (DIMN/64);
        mgemm_core<64,64,false,false,4>(dsm, g_d1h,g_d1l,HIDN, kth,ktl,DIMN,
                                        w1n,w1nh,w1nl,DIMN, BC,
                                        w1o,nullptr,nullptr,g_m1, gates, 0.f, 0,
                                        mt*64, nt*64);
    }
}

// ---------------- fused preamble: all splits + momentum zeroing, ONE launch ----------------
__device__ __forceinline__ void split_body(const float* __restrict__ s, bf* __restrict__ h,
                                           bf* __restrict__ l, int i)
{
    float4 v = *(const float4*)(s + i);
    float f[4] = {v.x, v.y, v.z, v.w};
    bf hv[4], lv[4];
    #pragma unroll
    for (int j = 0; j < 4; ++j) {
        hv[j] = __float2bfloat16_rn(f[j]);
        lv[j] = __float2bfloat16_rn(f[j] - __bfloat162float(hv[j]));
    }
    *(uint2*)(h + i) = *(uint2*)hv;
    *(uint2*)(l + i) = *(uint2*)lv;
}
// segments (blocks of 1024 elems): x 8192 | wk 1024 | wv 1024 | wq 1024 | wout 1024
// | w1 2048 | w2 2048 | zero m1 2048 | zero m2 2048   -> 20480 blocks total
__global__ void prep_k(const float* __restrict__ x,  const float* __restrict__ Wk,
                       const float* __restrict__ Wv, const float* __restrict__ Wq,
                       const float* __restrict__ Wo, const float* __restrict__ W1,
                       const float* __restrict__ W2)
{
    int b = blockIdx.x;
    const float* s; bf *h, *l; float* z = nullptr;
    if      (b <  8192){            s=x;  h=g_xh;      l=g_xl; }
    else if (b <  9216){ b-= 8192;  s=Wk; h=g_wkh;     l=g_wkl; }
    else if (b < 10240){ b-= 9216;  s=Wv; h=g_wvh;     l=g_wvl; }
    else if (b < 11264){ b-=10240;  s=Wq; h=g_wqh;     l=g_wql; }
    else if (b < 12288){ b-=11264;  s=Wo; h=g_woh;     l=g_wol; }
    else if (b < 14336){ b-=12288;  s=W1; h=g_w1h[1];  l=g_w1l[1]; }
    else if (b < 16384){ b-=14336;  s=W2; h=g_w2h[1];  l=g_w2l[1]; }
    else if (b < 18432){ b-=16384;  z=g_m1; s=nullptr; h=nullptr; l=nullptr; }
    else               { b-=18432;  z=g_m2; s=nullptr; h=nullptr; l=nullptr; }
    int i = (b*256 + threadIdx.x)*4;
    if (z){ *(float4*)(z + i) = make_float4(0.f,0.f,0.f,0.f); return; }
    split_body(s, h, l, i);
}

// ---------------- fused 3-way projection (k,q,v) ----------------
__global__ __launch_bounds__(128,3)
void proj_k()
{
    extern __shared__ __align__(16) char dsm[];
    int m0 = blockIdx.y*64, n0 = blockIdx.x*64;
    if (blockIdx.z == 0)
        mgemm_core<64,64,true,true,7>(dsm, g_xh,g_xl,DIMN, g_wkh,g_wkl,DIMN,
            g_kp,nullptr,nullptr,DIMN, DIMN, nullptr,nullptr,nullptr,nullptr,
            nullptr,0.f,0, m0, n0);
    else if (blockIdx.z == 1)
        mgemm_core<64,64,true,true,7>(dsm, g_xh,g_xl,DIMN, g_wqh,g_wql,DIMN,
            g_qp,nullptr,nullptr,DIMN, DIMN, nullptr,nullptr,nullptr,nullptr,
            nullptr,0.f,0, m0, n0);
    else
        mgemm_core<64,64,true,true,8>(dsm, g_xh,g_xl,DIMN, g_wvh,g_wvl,DIMN,
            nullptr,g_vph,g_vpl,DIMN, DIMN, nullptr,nullptr,nullptr,nullptr,
            nullptr,0.f,0, m0, n0);
}

// ---------------- fused l2 normalize (k then q), fp32 row -> hi/lo bf16 ----------------
__global__ void l2norm2_k()
{
    int bid = blockIdx.x;
    const float* src; bf *h, *l;
    if (bid < NTOK){ src = g_kp; h = g_kph; l = g_kpl; }
    else           { bid -= NTOK; src = g_qp; h = g_qph; l = g_qpl; }
    const float* r = src + (size_t)bid * DIMN;
    int t = threadIdx.x;
    float4 v = *(const float4*)(r + t*4);
    float ss = v.x*v.x + v.y*v.y + v.z*v.z + v.w*v.w;
    __shared__ float red[256];
    red[t] = ss; __syncthreads();
    for (int o = 128; o > 0; o >>= 1) { if (t < o) red[t] += red[t+o]; __syncthreads(); }
    float inv = rsqrtf(red[0] + EPSN);
    float f[4] = {v.x*inv, v.y*inv, v.z*inv, v.w*inv};
    bf hv[4], lv[4];
    #pragma unroll
    for (int j = 0; j < 4; ++j) {
        hv[j] = __float2bfloat16_rn(f[j]);
        lv[j] = __float2bfloat16_rn(f[j] - __bfloat162float(hv[j]));
    }
    size_t o4 = (size_t)bid * DIMN + t*4;
    *(uint2*)(h + o4) = *(uint2*)hv;
    *(uint2*)(l + o4) = *(uint2*)lv;
}

// ---------------- per-token gate dots ----------------
__global__ void gate_tok_k(const float* __restrict__ x,
                           const float* __restrict__ wlr,  const float* __restrict__ blr,
                           const float* __restrict__ wdec, const float* __restrict__ bdec,
                           const float* __restrict__ wmom, const float* __restrict__ bmom)
{
    int tok = blockIdx.x;
    int t = threadIdx.x;
    const float* xr = x + (size_t)tok * DIMN;
    float s0 = 0.f, s1 = 0.f, s2 = 0.f;
    for (int i = t; i < DIMN; i += 256) {
        float xi = xr[i];
        s0 += xi * wlr[i]; s1 += xi * wdec[i]; s2 += xi * wmom[i];
    }
    __shared__ float r0[256], r1[256], r2[256];
    r0[t] = s0; r1[t] = s1; r2[t] = s2; __syncthreads();
    for (int o = 128; o > 0; o >>= 1) {
        if (t < o) { r0[t] += r0[t+o]; r1[t] += r1[t+o]; r2[t] += r2[t+o]; }
        __syncthreads();
    }
    if (t == 0) {
        g_gate_tok[tok*3+0] = sigf(r0[0] + blr[0]);
        g_gate_tok[tok*3+1] = sigf(r1[0] + bdec[0]);
        g_gate_tok[tok*3+2] = sigf(r2[0] + bmom[0]);
    }
}

// ---------------- per-chunk gate means ----------------
__global__ void gate_chunk_k()
{
    int ch = blockIdx.x;
    int t = threadIdx.x;
    int b = t >> 6, ci = t & 63;
    int tok = b*SS + ch*CHK + ci;
    __shared__ float r0[256], r1[256], r2[256];
    r0[t] = g_gate_tok[tok*3+0];
    r1[t] = g_gate_tok[tok*3+1];
    r2[t] = g_gate_tok[tok*3+2];
    __syncthreads();
    for (int o = 128; o > 0; o >>= 1) {
        if (t < o) { r0[t] += r0[t+o]; r1[t] += r1[t+o]; r2[t] += r2[t+o]; }
        __syncthreads();
    }
    if (t == 0) {
        g_gates[ch*3+0] = r0[0] * (1.0f/BC);
        g_gates[ch*3+1] = r1[0] * (1.0f/BC);
        g_gates[ch*3+2] = r2[0] * (1.0f/BC);
    }
}

// smem sizes per config (3-stage async pipeline)
#define SM_A64 (3*(2*64+2*64)*40*2)   // 61440
#define SM_A32 (3*(2*32+2*64)*40*2)   // 46080
#define SM_R32 (2*(2*32+2*64)*40*2)   // 30720
#define SM_R64 (2*(2*64+2*64)*40*2)   // 40960

// ---------------- host orchestration ----------------
extern "C" void kernel_launch(void* const* d_in, const int* in_sizes, int n_in,
                              void* d_out, int out_size)
{
    const float* x    = (const float*)d_in[0];
    const float* Wk   = (const float*)d_in[1];
    const float* Wv   = (const float*)d_in[2];
    const float* Wq   = (const float*)d_in[3];
    const float* Wout = (const float*)d_in[4];
    const float* W1   = (const float*)d_in[5];
    const float* W2   = (const float*)d_in[6];
    const float* Wlr  = (const float*)d_in[7];
    const float* blr  = (const float*)d_in[8];
    const float* Wdec = (const float*)d_in[9];
    const float* bdec = (const float*)d_in[10];
    const float* Wmom = (const float*)d_in[11];
    const float* bmom = (const float*)d_in[12];
    float* out = (float*)d_out;

    static cudaStream_t s2 = nullptr;
    static cudaEvent_t evA = nullptr, evB0 = nullptr, evB1 = nullptr;
    if (!s2) {
        cudaStreamCreateWithFlags(&s2, cudaStreamNonBlocking);
        cudaEventCreateWithFlags(&evA,  cudaEventDisableTiming);
        cudaEventCreateWithFlags(&evB0, cudaEventDisableTiming);
        cudaEventCreateWithFlags(&evB1, cudaEventDisableTiming);
        cudaFuncSetAttribute(proj_k, cudaFuncAttributeMaxDynamicSharedMemorySize, SM_A64);
        cudaFuncSetAttribute(mgemm_k<64,64,true,true,0>, cudaFuncAttributeMaxDynamicSharedMemorySize, SM_A64);
        cudaFuncSetAttribute(mgemm_k<32,64,true,true,1>, cudaFuncAttributeMaxDynamicSharedMemorySize, SM_A32);
        cudaFuncSetAttribute(mgemm_k<32,64,true,true,2>, cudaFuncAttributeMaxDynamicSharedMemorySize, SM_A32);
        cudaFuncSetAttribute(mgemm_k<32,64,true,true,5>, cudaFuncAttributeMaxDynamicSharedMemorySize, SM_A32);
        cudaFuncSetAttribute(mgemm_k<32,64,true,true,6>, cudaFuncAttributeMaxDynamicSharedMemorySize, SM_A32);
        cudaFuncSetAttribute(mgemm_k<32,64,true,false,3>, cudaFuncAttributeMaxDynamicSharedMemorySize, SM_R32);
        cudaFuncSetAttribute(wupd_k, cudaFuncAttributeMaxDynamicSharedMemorySize, SM_R64);
    }

    bf *kph,*kpl,*qph,*qpl,*vph,*vpl;
    bf *a1h,*a1l,*d2h,*d2l,*d1h,*d1l,*aqh,*aql,*yh,*yl,*woh,*wol;
    float *h1,*gch;
    float *w1f0,*w1f1,*w2f0,*w2f1;
    bf *w1h0,*w1h1,*w1l0,*w1l1,*w2h0,*w2h1,*w2l0,*w2l1;

    cudaGetSymbolAddress((void**)&woh,g_woh);  cudaGetSymbolAddress((void**)&wol,g_wol);
    cudaGetSymbolAddress((void**)&kph,g_kph);  cudaGetSymbolAddress((void**)&kpl,g_kpl);
    cudaGetSymbolAddress((void**)&qph,g_qph);  cudaGetSymbolAddress((void**)&qpl,g_qpl);
    cudaGetSymbolAddress((void**)&vph,g_vph);  cudaGetSymbolAddress((void**)&vpl,g_vpl);
    cudaGetSymbolAddress((void**)&h1, g_h1);
    cudaGetSymbolAddress((void**)&a1h,g_a1h);  cudaGetSymbolAddress((void**)&a1l,g_a1l);
    cudaGetSymbolAddress((void**)&d2h,g_d2h);  cudaGetSymbolAddress((void**)&d2l,g_d2l);
    cudaGetSymbolAddress((void**)&d1h,g_d1h);  cudaGetSymbolAddress((void**)&d1l,g_d1l);
    cudaGetSymbolAddress((void**)&aqh,g_aqh);  cudaGetSymbolAddress((void**)&aql,g_aql);
    cudaGetSymbolAddress((void**)&yh, g_yh);   cudaGetSymbolAddress((void**)&yl, g_yl);
    cudaGetSymbolAddress((void**)&gch,g_gates);
    { void* p;
      cudaGetSymbolAddress(&p, g_w1f); w1f0=(float*)p; w1f1=w1f0+HIDN*DIMN;
      cudaGetSymbolAddress(&p, g_w1h); w1h0=(bf*)p;    w1h1=w1h0+HIDN*DIMN;
      cudaGetSymbolAddress(&p, g_w1l); w1l0=(bf*)p;    w1l1=w1l0+HIDN*DIMN;
      cudaGetSymbolAddress(&p, g_w2f); w2f0=(float*)p; w2f1=w2f0+DIMN*HIDN;
      cudaGetSymbolAddress(&p, g_w2h); w2h0=(bf*)p;    w2h1=w2h0+DIMN*HIDN;
      cudaGetSymbolAddress(&p, g_w2l); w2l0=(bf*)p;    w2l1=w2l0+DIMN*HIDN;
    }

    // launch 0: fused splits + momentum zeroing
    prep_k<<<20480, 256>>>(x, Wk, Wv, Wq, Wout, W1, W2);
    // launches 1,2: gates
    gate_tok_k<<<NTOK, 256>>>(x, Wlr, blr, Wdec, bdec, Wmom, bmom);
    gate_chunk_k<<<NCH, 256>>>();
    // launch 3: fused projections (k,q,v)
    proj_k<<<dim3(DIMN/64, NTOK/64, 3),128,SM_A64>>>();
    // launch 4: fused l2norm (k+q)
    l2norm2_k<<<2*NTOK,256>>>();

    for (int ch = 0; ch < NCH; ++ch) {
        size_t co = (size_t)ch*BC*DIMN;
        const bf *kth = kph+co, *ktl = kpl+co;
        const bf *qth = qph+co, *qtl = qpl+co;
        const bf *vth = vph+co, *vtl = vpl+co;
        int wi = ch & 1;
        int ri = 1 - wi;
        const float* w1o = (ch == 0) ? W1 : (ri ? w1f1 : w1f0);
        const float* w2o = (ch == 0) ? W2 : (ri ? w2f1 : w2f0);
        const bf *w1rh = ri ? w1h1 : w1h0, *w1rl = ri ? w1l1 : w1l0;
        const bf *w2rh = ri ? w2h1 : w2h0, *w2rl = ri ? w2l1 : w2l0;
        float* w1n = wi ? w1f1 : w1f0;
        float* w2n = wi ? w2f1 : w2f0;
        bf *w1nh = wi ? w1h1 : w1h0, *w1nl = wi ? w1l1 : w1l0;
        bf *w2nh = wi ? w2h1 : w2h0, *w2nl = wi ? w2l1 : w2l0;
        const float* gp3 = gch + ch*3;

        // forward + grads on stream 0
        mgemm_k<32,64,true,true,1><<<dim3(HIDN/64, BC/32),128,SM_A32>>>(
            kth,ktl,DIMN, w1rh,w1rl,DIMN, h1,a1h,a1l,HIDN, DIMN,
            nullptr,nullptr,nullptr,nullptr, nullptr,0.f,0);
        mgemm_k<32,64,true,true,2><<<dim3(DIMN/64, BC/32),128,SM_A32>>>(
            a1h,a1l,HIDN, w2rh,w2rl,HIDN, nullptr,d2h,d2l,DIMN, HIDN,
            nullptr,vth,vtl,nullptr, nullptr,SCALE_CONST,0);
        mgemm_k<32,64,true,false,3><<<dim3(HIDN/64, BC/32),128,SM_R32>>>(
            d2h,d2l,DIMN, w2rh,w2rl,HIDN, nullptr,d1h,d1l,HIDN, DIMN,
            h1,nullptr,nullptr,nullptr, nullptr,0.f,0);
        // wupd(ch) rewrites weight slot (ch&1): wait until retrieval of ch-2 (same slot) finished
        if (ch >= 2) cudaStreamWaitEvent(0, (ch & 1) ? evB1 : evB0, 0);
        wupd_k<<<(HIDN/64)*(DIMN/64)*2,128,SM_R64>>>(
            kth,ktl, w2n,w2nh,w2nl, w2o, w1n,w1nh,w1nl, w1o, gp3);
        // retrieval on stream 2, overlapped with next chunk's forward
        cudaEventRecord(evA, 0);
        cudaStreamWaitEvent(s2, evA, 0);
        mgemm_k<32,64,true,true,5><<<dim3(HIDN/64, BC/32),128,SM_A32,s2>>>(
            qth,qtl,DIMN, w1nh,w1nl,DIMN, nullptr,aqh,aql,HIDN, DIMN,
            nullptr,nullptr,nullptr,nullptr, nullptr,0.f,0);
        mgemm_k<32,64,true,true,6><<<dim3(DIMN/64, BC/32),128,SM_A32,s2>>>(
            aqh,aql,HIDN, w2nh,w2nl,HIDN, nullptr,yh,yl,DIMN, HIDN,
            nullptr,nullptr,nullptr,nullptr, nullptr,0.f,ch*CHK);
        cudaEventRecord((ch & 1) ? evB1 : evB0, s2);
    }

    // join retrieval stream, then output projection
    cudaStreamWaitEvent(0, ((NCH-1) & 1) ? evB1 : evB0, 0);
    mgemm_k<64,64,true,true,0><<<dim3(DIMN/64, NTOK/64),128,SM_A64>>>(
        yh,yl,DIMN, woh,wol,DIMN, out,nullptr,nullptr,DIMN, DIMN,
        nullptr,nullptr,nullptr,nullptr, nullptr,0.f,0);
}

// round 17
// speedup vs baseline: 1.2776x; 1.0542x over previous
#include <cuda_runtime.h>
#include <cuda_bf16.h>
#include <math.h>

// ---------------- problem constants ----------------
#define DIMN 1024
#define HIDN 2048
#define BB   4
#define SS   2048
#define CHK  64
#define NCH  32        // SS/CHK
#define BC   256       // BB*CHK
#define NTOK 8192      // BB*SS
#define EPSN 1e-8f
#define SCALE_CONST (2.0f/(BB*CHK*DIMN))

using bf = __nv_bfloat16;

// ---------------- device scratch (no runtime allocs allowed) ----------------
__device__ bf g_xh[NTOK*DIMN],  g_xl[NTOK*DIMN];
__device__ bf g_wkh[DIMN*DIMN], g_wkl[DIMN*DIMN];
__device__ bf g_wvh[DIMN*DIMN], g_wvl[DIMN*DIMN];
__device__ bf g_wqh[DIMN*DIMN], g_wql[DIMN*DIMN];
__device__ bf g_woh[DIMN*DIMN], g_wol[DIMN*DIMN];
__device__ float g_kp[NTOK*DIMN];
__device__ float g_qp[NTOK*DIMN];
__device__ bf g_kph[NTOK*DIMN], g_kpl[NTOK*DIMN];
__device__ bf g_qph[NTOK*DIMN], g_qpl[NTOK*DIMN];
__device__ bf g_vph[NTOK*DIMN], g_vpl[NTOK*DIMN];
__device__ float g_h1[BC*HIDN];
__device__ bf g_a1h[BC*HIDN], g_a1l[BC*HIDN];
__device__ bf g_d2h[BC*DIMN], g_d2l[BC*DIMN];
__device__ bf g_d1h[BC*HIDN], g_d1l[BC*HIDN];
__device__ bf g_aqh[BC*HIDN], g_aql[BC*HIDN];
__device__ bf g_yh[NTOK*DIMN], g_yl[NTOK*DIMN];
__device__ float g_w1f[2][HIDN*DIMN];
__device__ bf    g_w1h[2][HIDN*DIMN], g_w1l[2][HIDN*DIMN];
__device__ float g_w2f[2][DIMN*HIDN];
__device__ bf    g_w2h[2][DIMN*HIDN], g_w2l[2][DIMN*HIDN];
__device__ float g_m1[HIDN*DIMN];
__device__ float g_m2[DIMN*HIDN];
__device__ float g_gate_tok[NTOK*3];
__device__ float g_gates[NCH*3];

// ---------------- math helpers ----------------
__device__ __forceinline__ float sigf(float x){ return 1.0f/(1.0f+expf(-x)); }
__device__ __forceinline__ float siluf(float x){ return x*sigf(x); }
__device__ __forceinline__ float siluderivf(float x){ float s=sigf(x); return s*(1.0f + x*(1.0f-s)); }
__device__ __forceinline__ float clip1f(float x){ return fminf(fmaxf(x,-1.0f),1.0f); }
__device__ __forceinline__ void store_hl(bf* H, bf* L, size_t idx, float v){
    bf h = __float2bfloat16_rn(v);
    H[idx] = h;
    L[idx] = __float2bfloat16_rn(v - __bfloat162float(h));
}

// ---------------- mma / ldmatrix / cp.async primitives ----------------
__device__ __forceinline__ void mma_bf16(float* d, const unsigned* a, const unsigned* b){
    asm volatile(
        "mma.sync.aligned.m16n8k16.row.col.f32.bf16.bf16.f32 "
        "{%0,%1,%2,%3}, {%4,%5,%6,%7}, {%8,%9}, {%0,%1,%2,%3};\n"
        : "+f"(d[0]), "+f"(d[1]), "+f"(d[2]), "+f"(d[3])
        : "r"(a[0]), "r"(a[1]), "r"(a[2]), "r"(a[3]), "r"(b[0]), "r"(b[1]));
}
__device__ __forceinline__ void ldsm4(unsigned* r, const bf* p){
    unsigned a = (unsigned)__cvta_generic_to_shared(p);
    asm volatile("ldmatrix.sync.aligned.m8n8.x4.shared.b16 {%0,%1,%2,%3}, [%4];\n"
        : "=r"(r[0]), "=r"(r[1]), "=r"(r[2]), "=r"(r[3]) : "r"(a));
}
__device__ __forceinline__ void cpa16(bf* s, const bf* g){
    unsigned sa = (unsigned)__cvta_generic_to_shared(s);
    asm volatile("cp.async.cg.shared.global [%0], [%1], 16;\n" :: "r"(sa), "l"(g));
}
__device__ __forceinline__ void cp_commit(){ asm volatile("cp.async.commit_group;\n"); }
template<int N> __device__ __forceinline__ void cp_wait(){ asm volatile("cp.async.wait_group %0;\n" :: "n"(N)); }

// ---------------- register-staged loader (KM=false transpose path) ----------------
template<int R, bool KM, int KC, int KS>
struct Loader {
    static constexpr int CH = (R*KC)/(128*8);
    uint4 vh[CH], vl[CH];
    __device__ __forceinline__ void fetch(const bf* __restrict__ Ph, const bf* __restrict__ Pl,
                                          int ld, int r0, int k0, int tid){
        #pragma unroll
        for (int c = 0; c < CH; ++c){
            int id = tid + c*128;
            if constexpr (KM){
                int r = id/(KC/8), kq = (id%(KC/8))*8;
                size_t off = (size_t)(r0+r)*ld + k0 + kq;
                vh[c] = *(const uint4*)(Ph + off);
                vl[c] = *(const uint4*)(Pl + off);
            } else {
                int k = id/(R/8), rq = (id%(R/8))*8;
                size_t off = (size_t)(k0+k)*ld + r0 + rq;
                vh[c] = *(const uint4*)(Ph + off);
                vl[c] = *(const uint4*)(Pl + off);
            }
        }
    }
    __device__ __forceinline__ void store(bf* Sh, bf* Sl, int tid){
        #pragma unroll
        for (int c = 0; c < CH; ++c){
            int id = tid + c*128;
            if constexpr (KM){
                int r = id/(KC/8), kq = (id%(KC/8))*8;
                *(uint4*)(Sh + r*KS + kq) = vh[c];
                *(uint4*)(Sl + r*KS + kq) = vl[c];
            } else {
                int k = id/(R/8), rq = (id%(R/8))*8;
                const bf* ph = (const bf*)&vh[c];
                const bf* pl = (const bf*)&vl[c];
                #pragma unroll
                for (int j = 0; j < 8; ++j){
                    Sh[(rq+j)*KS + k] = ph[j];
                    Sl[(rq+j)*KS + k] = pl[j];
                }
            }
        }
    }
};

// ---------------- GEMM core: C[M,N] = sum_k A(m,k)*B(n,k) ----------------
// EP: 0 C=acc | 1 C=acc,Ch/Cl=silu | 2 Ch/Cl=scale*clip(acc-(x0h+x0l)) | 3 Ch/Cl=acc*silu'(f0)
//     4 weight update | 5 Ch/Cl=silu | 6 Ch/Cl=acc natural-layout | 7 C=silu perm | 8 Ch/Cl=silu perm
template<int BM,int BN,bool AKM,bool BKM,int EP>
__device__ __forceinline__ void mgemm_core(
    char* dsm,
    const bf* __restrict__ Ah, const bf* __restrict__ Al, int lda,
    const bf* __restrict__ Bh, const bf* __restrict__ Bl, int ldb,
    float* __restrict__ C, bf* __restrict__ Ch, bf* __restrict__ Cl, int ldc,
    int K,
    const float* __restrict__ f0,
    const bf* __restrict__ x0h, const bf* __restrict__ x0l,
    float* __restrict__ f1,
    const float* __restrict__ gates,
    float scale, int base, int m0, int n0)
{
    constexpr int KC = 32;
    constexpr int KS = 40;
    constexpr int NI = (BM == 64) ? 4 : 2;
    constexpr int NJ = NI/2;
    constexpr int ASZ = BM*KS, BSZ = BN*KS;
    constexpr int STRIDE = 2*ASZ + 2*BSZ;

    const int tid  = threadIdx.x;
    const int lane = tid & 31;
    const int wid  = tid >> 5;
    const int g    = lane >> 2;
    const int tg   = lane & 3;
    const int wm = (BM == 64) ? (wid >> 1) * 32 : 0;
    const int wn = (BM == 64) ? (wid & 1) * 32 : wid * 16;
    const int aoff = (lane & 15)*KS + (lane >> 4)*8;
    const int boff = ((lane & 7) + ((lane >> 4) & 1)*8)*KS + ((lane >> 3) & 1)*8;

    bf* base_s = (bf*)dsm;

    float accm[2][NI][4] = {};
    float accc[2][NI][4] = {};

    auto compute_tile = [&](const bf* Ahs, const bf* Als, const bf* Bhs, const bf* Bls){
        #pragma unroll
        for (int kt = 0; kt < KC; kt += 16) {
            unsigned ah[2][4], al_[2][4], b2h[NJ][4], b2l[NJ][4];
            #pragma unroll
            for (int mi = 0; mi < 2; ++mi) {
                ldsm4(ah[mi],  Ahs + (wm + mi*16)*KS + kt + aoff);
                ldsm4(al_[mi], Als + (wm + mi*16)*KS + kt + aoff);
            }
            #pragma unroll
            for (int nj = 0; nj < NJ; ++nj) {
                ldsm4(b2h[nj], Bhs + (wn + nj*16)*KS + kt + boff);
                ldsm4(b2l[nj], Bls + (wn + nj*16)*KS + kt + boff);
            }
            #pragma unroll
            for (int mi = 0; mi < 2; ++mi)
                #pragma unroll
                for (int nj = 0; nj < NJ; ++nj) {
                    mma_bf16(accm[mi][nj*2+0], ah[mi],  b2h[nj]+0);
                    mma_bf16(accm[mi][nj*2+1], ah[mi],  b2h[nj]+2);
                    mma_bf16(accc[mi][nj*2+0], ah[mi],  b2l[nj]+0);
                    mma_bf16(accc[mi][nj*2+1], ah[mi],  b2l[nj]+2);
                    mma_bf16(accc[mi][nj*2+0], al_[mi], b2h[nj]+0);
                    mma_bf16(accc[mi][nj*2+1], al_[mi], b2h[nj]+2);
                }
        }
    };

    if constexpr (AKM && BKM) {
        // ---- 2-stage cp.async pipeline (4 blocks/SM residency) ----
        constexpr int STG = 2;
        const int KT = K / KC;
        auto issue = [&](int s, int k0){
            bf* dAh = base_s + s*STRIDE; bf* dAl = dAh + ASZ;
            bf* dBh = dAl + ASZ;         bf* dBl = dBh + BSZ;
            #pragma unroll
            for (int c2 = 0; c2 < (BM*4)/128; ++c2){
                int id = tid + c2*128; int r = id >> 2, kq = (id & 3)*8;
                size_t off = (size_t)(m0+r)*lda + k0 + kq;
                cpa16(dAh + r*KS + kq, Ah + off);
                cpa16(dAl + r*KS + kq, Al + off);
            }
            #pragma unroll
            for (int c2 = 0; c2 < (BN*4)/128; ++c2){
                int id = tid + c2*128; int r = id >> 2, kq = (id & 3)*8;
                size_t off = (size_t)(n0+r)*ldb + k0 + kq;
                cpa16(dBh + r*KS + kq, Bh + off);
                cpa16(dBl + r*KS + kq, Bl + off);
            }
            cp_commit();
        };
        int fetch = 0;
        for (; fetch < STG-1 && fetch < KT; ++fetch) issue(fetch, fetch*KC);
        for (int c = 0; c < KT; ++c){
            int nrem = fetch - 1 - c;
            if (nrem >= 1) cp_wait<1>(); else cp_wait<0>();
            __syncthreads();
            if (fetch < KT){ issue(fetch % STG, fetch*KC); ++fetch; }
            int s = c % STG;
            bf* pAh = base_s + s*STRIDE; bf* pAl = pAh + ASZ;
            bf* pBh = pAl + ASZ;         bf* pBl = pBh + BSZ;
            compute_tile(pAh, pAl, pBh, pBl);
        }
    } else {
        // ---- register-staged 2-buffer path (handles transpose loads) ----
        Loader<BM,AKM,KC,KS> la;
        Loader<BN,BKM,KC,KS> lb;
        bf* A0[2]; bf* A1[2]; bf* B0[2]; bf* B1[2];
        #pragma unroll
        for (int b = 0; b < 2; ++b){
            bf* p = base_s + b*STRIDE;
            A0[b] = p; A1[b] = p + ASZ; B0[b] = p + 2*ASZ; B1[b] = p + 2*ASZ + BSZ;
        }
        la.fetch(Ah, Al, lda, m0, 0, tid);
        lb.fetch(Bh, Bl, ldb, n0, 0, tid);
        la.store(A0[0], A1[0], tid);
        lb.store(B0[0], B1[0], tid);
        __syncthreads();
        int cur = 0;
        for (int k0 = 0; k0 < K; k0 += KC) {
            bool more = (k0 + KC) < K;
            if (more) {
                la.fetch(Ah, Al, lda, m0, k0 + KC, tid);
                lb.fetch(Bh, Bl, ldb, n0, k0 + KC, tid);
            }
            compute_tile(A0[cur], A1[cur], B0[cur], B1[cur]);
            if (more) {
                la.store(A0[cur^1], A1[cur^1], tid);
                lb.store(B0[cur^1], B1[cur^1], tid);
                __syncthreads();
                cur ^= 1;
            }
        }
    }

    // ---- epilogue ----
    float lrg = 0.f, alg = 0.f, etg = 0.f;
    if constexpr (EP == 4) { lrg = gates[0]; alg = gates[1]; etg = gates[2]; }

    #pragma unroll
    for (int mi = 0; mi < 2; ++mi)
    #pragma unroll
    for (int rr = 0; rr < 2; ++rr) {
        int m = m0 + wm + mi*16 + rr*8 + g;
        size_t crow;
        if constexpr (EP == 6) {
            int b = m >> 6, ci = m & 63;
            crow = (size_t)(b*SS + base + ci) * ldc;
        } else if constexpr (EP == 7 || EP == 8) {
            int b = m >> 11, s = m & (SS-1);
            crow = (size_t)((s >> 6)*BC + b*CHK + (s & 63)) * ldc;
        } else {
            crow = (size_t)m * ldc;
        }
        size_t srow = (size_t)m * ldc;
        #pragma unroll
        for (int ni = 0; ni < NI; ++ni) {
            int n = n0 + wn + ni*8 + tg*2;
            #pragma unroll
            for (int cc = 0; cc < 2; ++cc) {
                float v = accm[mi][ni][rr*2 + cc] + accc[mi][ni][rr*2 + cc];
                size_t idx  = crow + n + cc;
                size_t sidx = srow + n + cc;
                if constexpr (EP == 0) C[idx] = v;
                else if constexpr (EP == 1) { C[idx] = v; store_hl(Ch, Cl, idx, siluf(v)); }
                else if constexpr (EP == 2) {
                    float vv = __bfloat162float(x0h[sidx]) + __bfloat162float(x0l[sidx]);
                    store_hl(Ch, Cl, idx, scale * clip1f(v - vv));
                }
                else if constexpr (EP == 3) store_hl(Ch, Cl, idx, v * siluderivf(f0[sidx]));
                else if constexpr (EP == 4) {
                    float gg = clip1f(v);
                    float mn = etg * f1[idx] - lrg * gg;
                    f1[idx] = mn;
                    float w = (1.0f - alg) * f0[idx] + mn;
                    C[idx] = w;
                    store_hl(Ch, Cl, idx, w);
                }
                else if constexpr (EP == 5) store_hl(Ch, Cl, idx, siluf(v));
                else if constexpr (EP == 6) store_hl(Ch, Cl, idx, v);
                else if constexpr (EP == 7) C[idx] = siluf(v);
                else if constexpr (EP == 8) store_hl(Ch, Cl, idx, siluf(v));
            }
        }
    }
}

template<int BM,int BN,bool AKM,bool BKM,int EP>
__global__ __launch_bounds__(128,4)
void mgemm_k(const bf* __restrict__ Ah, const bf* __restrict__ Al, int lda,
             const bf* __restrict__ Bh, const bf* __restrict__ Bl, int ldb,
             float* __restrict__ C, bf* __restrict__ Ch, bf* __restrict__ Cl, int ldc,
             int K,
             const float* __restrict__ f0,
             const bf* __restrict__ x0h, const bf* __restrict__ x0l,
             float* __restrict__ f1,
             const float* __restrict__ gates, float scale, int base)
{
    extern __shared__ __align__(16) char dsm[];
    mgemm_core<BM,BN,AKM,BKM,EP>(dsm, Ah,Al,lda, Bh,Bl,ldb, C,Ch,Cl,ldc, K,
                                 f0,x0h,x0l,f1, gates, scale, base,
                                 blockIdx.y*BM, blockIdx.x*BN);
}

// fused weight updates (w2 grad + w1 grad), both EP4, 64x64 tiles, K=BC
__global__ __launch_bounds__(128,4)
void wupd_k(const bf* __restrict__ kth, const bf* __restrict__ ktl,
            float* __restrict__ w2n, bf* __restrict__ w2nh, bf* __restrict__ w2nl,
            const float* __restrict__ w2o,
            float* __restrict__ w1n, bf* __restrict__ w1nh, bf* __restrict__ w1nl,
            const float* __restrict__ w1o,
            const float* __restrict__ gates)
{
    extern __shared__ __align__(16) char dsm[];
    int bx = blockIdx.x;
    constexpr int T2 = (HIDN/64)*(DIMN/64);
    if (bx < T2) {
        int nt = bx % (HIDN/64), mt = bx / (HIDN/64);
        mgemm_core<64,64,false,false,4>(dsm, g_d2h,g_d2l,DIMN, g_a1h,g_a1l,HIDN,
                                        w2n,w2nh,w2nl,HIDN, BC,
                                        w2o,nullptr,nullptr,g_m2, gates, 0.f, 0,
                                        mt*64, nt*64);
    } else {
        int i = bx - T2;
        int nt = i % (DIMN/64), mt = i / (DIMN/64);
        mgemm_core<64,64,false,false,4>(dsm, g_d1h,g_d1l,HIDN, kth,ktl,DIMN,
                                        w1n,w1nh,w1nl,DIMN, BC,
                                        w1o,nullptr,nullptr,g_m1, gates, 0.f, 0,
                                        mt*64, nt*64);
    }
}

// ---------------- fused preamble: all splits + momentum zeroing, ONE launch ----------------
__device__ __forceinline__ void split_body(const float* __restrict__ s, bf* __restrict__ h,
                                           bf* __restrict__ l, int i)
{
    float4 v = *(const float4*)(s + i);
    float f[4] = {v.x, v.y, v.z, v.w};
    bf hv[4], lv[4];
    #pragma unroll
    for (int j = 0; j < 4; ++j) {
        hv[j] = __float2bfloat16_rn(f[j]);
        lv[j] = __float2bfloat16_rn(f[j] - __bfloat162float(hv[j]));
    }
    *(uint2*)(h + i) = *(uint2*)hv;
    *(uint2*)(l + i) = *(uint2*)lv;
}
// segments (blocks of 1024 elems): x 8192 | wk 1024 | wv 1024 | wq 1024 | wout 1024
// | w1 2048 | w2 2048 | zero m1 2048 | zero m2 2048   -> 20480 blocks total
__global__ void prep_k(const float* __restrict__ x,  const float* __restrict__ Wk,
                       const float* __restrict__ Wv, const float* __restrict__ Wq,
                       const float* __restrict__ Wo, const float* __restrict__ W1,
                       const float* __restrict__ W2)
{
    int b = blockIdx.x;
    const float* s; bf *h, *l; float* z = nullptr;
    if      (b <  8192){            s=x;  h=g_xh;      l=g_xl; }
    else if (b <  9216){ b-= 8192;  s=Wk; h=g_wkh;     l=g_wkl; }
    else if (b < 10240){ b-= 9216;  s=Wv; h=g_wvh;     l=g_wvl; }
    else if (b < 11264){ b-=10240;  s=Wq; h=g_wqh;     l=g_wql; }
    else if (b < 12288){ b-=11264;  s=Wo; h=g_woh;     l=g_wol; }
    else if (b < 14336){ b-=12288;  s=W1; h=g_w1h[1];  l=g_w1l[1]; }
    else if (b < 16384){ b-=14336;  s=W2; h=g_w2h[1];  l=g_w2l[1]; }
    else if (b < 18432){ b-=16384;  z=g_m1; s=nullptr; h=nullptr; l=nullptr; }
    else               { b-=18432;  z=g_m2; s=nullptr; h=nullptr; l=nullptr; }
    int i = (b*256 + threadIdx.x)*4;
    if (z){ *(float4*)(z + i) = make_float4(0.f,0.f,0.f,0.f); return; }
    split_body(s, h, l, i);
}

// ---------------- fused 3-way projection (k,q,v) ----------------
__global__ __launch_bounds__(128,4)
void proj_k()
{
    extern __shared__ __align__(16) char dsm[];
    int m0 = blockIdx.y*64, n0 = blockIdx.x*64;
    if (blockIdx.z == 0)
        mgemm_core<64,64,true,true,7>(dsm, g_xh,g_xl,DIMN, g_wkh,g_wkl,DIMN,
            g_kp,nullptr,nullptr,DIMN, DIMN, nullptr,nullptr,nullptr,nullptr,
            nullptr,0.f,0, m0, n0);
    else if (blockIdx.z == 1)
        mgemm_core<64,64,true,true,7>(dsm, g_xh,g_xl,DIMN, g_wqh,g_wql,DIMN,
            g_qp,nullptr,nullptr,DIMN, DIMN, nullptr,nullptr,nullptr,nullptr,
            nullptr,0.f,0, m0, n0);
    else
        mgemm_core<64,64,true,true,8>(dsm, g_xh,g_xl,DIMN, g_wvh,g_wvl,DIMN,
            nullptr,g_vph,g_vpl,DIMN, DIMN, nullptr,nullptr,nullptr,nullptr,
            nullptr,0.f,0, m0, n0);
}

// ---------------- fused l2 normalize (k then q), fp32 row -> hi/lo bf16 ----------------
__global__ void l2norm2_k()
{
    int bid = blockIdx.x;
    const float* src; bf *h, *l;
    if (bid < NTOK){ src = g_kp; h = g_kph; l = g_kpl; }
    else           { bid -= NTOK; src = g_qp; h = g_qph; l = g_qpl; }
    const float* r = src + (size_t)bid * DIMN;
    int t = threadIdx.x;
    float4 v = *(const float4*)(r + t*4);
    float ss = v.x*v.x + v.y*v.y + v.z*v.z + v.w*v.w;
    __shared__ float red[256];
    red[t] = ss; __syncthreads();
    for (int o = 128; o > 0; o >>= 1) { if (t < o) red[t] += red[t+o]; __syncthreads(); }
    float inv = rsqrtf(red[0] + EPSN);
    float f[4] = {v.x*inv, v.y*inv, v.z*inv, v.w*inv};
    bf hv[4], lv[4];
    #pragma unroll
    for (int j = 0; j < 4; ++j) {
        hv[j] = __float2bfloat16_rn(f[j]);
        lv[j] = __float2bfloat16_rn(f[j] - __bfloat162float(hv[j]));
    }
    size_t o4 = (size_t)bid * DIMN + t*4;
    *(uint2*)(h + o4) = *(uint2*)hv;
    *(uint2*)(l + o4) = *(uint2*)lv;
}

// ---------------- per-token gate dots ----------------
__global__ void gate_tok_k(const float* __restrict__ x,
                           const float* __restrict__ wlr,  const float* __restrict__ blr,
                           const float* __restrict__ wdec, const float* __restrict__ bdec,
                           const float* __restrict__ wmom, const float* __restrict__ bmom)
{
    int tok = blockIdx.x;
    int t = threadIdx.x;
    const float* xr = x + (size_t)tok * DIMN;
    float s0 = 0.f, s1 = 0.f, s2 = 0.f;
    for (int i = t; i < DIMN; i += 256) {
        float xi = xr[i];
        s0 += xi * wlr[i]; s1 += xi * wdec[i]; s2 += xi * wmom[i];
    }
    __shared__ float r0[256], r1[256], r2[256];
    r0[t] = s0; r1[t] = s1; r2[t] = s2; __syncthreads();
    for (int o = 128; o > 0; o >>= 1) {
        if (t < o) { r0[t] += r0[t+o]; r1[t] += r1[t+o]; r2[t] += r2[t+o]; }
        __syncthreads();
    }
    if (t == 0) {
        g_gate_tok[tok*3+0] = sigf(r0[0] + blr[0]);
        g_gate_tok[tok*3+1] = sigf(r1[0] + bdec[0]);
        g_gate_tok[tok*3+2] = sigf(r2[0] + bmom[0]);
    }
}

// ---------------- per-chunk gate means ----------------
__global__ void gate_chunk_k()
{
    int ch = blockIdx.x;
    int t = threadIdx.x;
    int b = t >> 6, ci = t & 63;
    int tok = b*SS + ch*CHK + ci;
    __shared__ float r0[256], r1[256], r2[256];
    r0[t] = g_gate_tok[tok*3+0];
    r1[t] = g_gate_tok[tok*3+1];
    r2[t] = g_gate_tok[tok*3+2];
    __syncthreads();
    for (int o = 128; o > 0; o >>= 1) {
        if (t < o) { r0[t] += r0[t+o]; r1[t] += r1[t+o]; r2[t] += r2[t+o]; }
        __syncthreads();
    }
    if (t == 0) {
        g_gates[ch*3+0] = r0[0] * (1.0f/BC);
        g_gates[ch*3+1] = r1[0] * (1.0f/BC);
        g_gates[ch*3+2] = r2[0] * (1.0f/BC);
    }
}

// smem sizes per config (2-stage async pipeline)
#define SM_A64 (2*(2*64+2*64)*40*2)   // 40960
#define SM_A32 (2*(2*32+2*64)*40*2)   // 30720
#define SM_R32 (2*(2*32+2*64)*40*2)   // 30720
#define SM_R64 (2*(2*64+2*64)*40*2)   // 40960

// ---------------- host orchestration ----------------
extern "C" void kernel_launch(void* const* d_in, const int* in_sizes, int n_in,
                              void* d_out, int out_size)
{
    const float* x    = (const float*)d_in[0];
    const float* Wk   = (const float*)d_in[1];
    const float* Wv   = (const float*)d_in[2];
    const float* Wq   = (const float*)d_in[3];
    const float* Wout = (const float*)d_in[4];
    const float* W1   = (const float*)d_in[5];
    const float* W2   = (const float*)d_in[6];
    const float* Wlr  = (const float*)d_in[7];
    const float* blr  = (const float*)d_in[8];
    const float* Wdec = (const float*)d_in[9];
    const float* bdec = (const float*)d_in[10];
    const float* Wmom = (const float*)d_in[11];
    const float* bmom = (const float*)d_in[12];
    float* out = (float*)d_out;

    static cudaStream_t s2 = nullptr;
    static cudaEvent_t evA = nullptr, evB0 = nullptr, evB1 = nullptr;
    if (!s2) {
        cudaStreamCreateWithFlags(&s2, cudaStreamNonBlocking);
        cudaEventCreateWithFlags(&evA,  cudaEventDisableTiming);
        cudaEventCreateWithFlags(&evB0, cudaEventDisableTiming);
        cudaEventCreateWithFlags(&evB1, cudaEventDisableTiming);
        cudaFuncSetAttribute(proj_k, cudaFuncAttributeMaxDynamicSharedMemorySize, SM_A64);
        cudaFuncSetAttribute(mgemm_k<64,64,true,true,0>, cudaFuncAttributeMaxDynamicSharedMemorySize, SM_A64);
        cudaFuncSetAttribute(mgemm_k<32,64,true,true,1>, cudaFuncAttributeMaxDynamicSharedMemorySize, SM_A32);
        cudaFuncSetAttribute(mgemm_k<32,64,true,true,2>, cudaFuncAttributeMaxDynamicSharedMemorySize, SM_A32);
        cudaFuncSetAttribute(mgemm_k<32,64,true,true,5>, cudaFuncAttributeMaxDynamicSharedMemorySize, SM_A32);
        cudaFuncSetAttribute(mgemm_k<32,64,true,true,6>, cudaFuncAttributeMaxDynamicSharedMemorySize, SM_A32);
        cudaFuncSetAttribute(mgemm_k<32,64,true,false,3>, cudaFuncAttributeMaxDynamicSharedMemorySize, SM_R32);
        cudaFuncSetAttribute(wupd_k, cudaFuncAttributeMaxDynamicSharedMemorySize, SM_R64);
    }

    bf *kph,*kpl,*qph,*qpl,*vph,*vpl;
    bf *a1h,*a1l,*d2h,*d2l,*d1h,*d1l,*aqh,*aql,*yh,*yl,*woh,*wol;
    float *h1,*gch;
    float *w1f0,*w1f1,*w2f0,*w2f1;
    bf *w1h0,*w1h1,*w1l0,*w1l1,*w2h0,*w2h1,*w2l0,*w2l1;

    cudaGetSymbolAddress((void**)&woh,g_woh);  cudaGetSymbolAddress((void**)&wol,g_wol);
    cudaGetSymbolAddress((void**)&kph,g_kph);  cudaGetSymbolAddress((void**)&kpl,g_kpl);
    cudaGetSymbolAddress((void**)&qph,g_qph);  cudaGetSymbolAddress((void**)&qpl,g_qpl);
    cudaGetSymbolAddress((void**)&vph,g_vph);  cudaGetSymbolAddress((void**)&vpl,g_vpl);
    cudaGetSymbolAddress((void**)&h1, g_h1);
    cudaGetSymbolAddress((void**)&a1h,g_a1h);  cudaGetSymbolAddress((void**)&a1l,g_a1l);
    cudaGetSymbolAddress((void**)&d2h,g_d2h);  cudaGetSymbolAddress((void**)&d2l,g_d2l);
    cudaGetSymbolAddress((void**)&d1h,g_d1h);  cudaGetSymbolAddress((void**)&d1l,g_d1l);
    cudaGetSymbolAddress((void**)&aqh,g_aqh);  cudaGetSymbolAddress((void**)&aql,g_aql);
    cudaGetSymbolAddress((void**)&yh, g_yh);   cudaGetSymbolAddress((void**)&yl, g_yl);
    cudaGetSymbolAddress((void**)&gch,g_gates);
    { void* p;
      cudaGetSymbolAddress(&p, g_w1f); w1f0=(float*)p; w1f1=w1f0+HIDN*DIMN;
      cudaGetSymbolAddress(&p, g_w1h); w1h0=(bf*)p;    w1h1=w1h0+HIDN*DIMN;
      cudaGetSymbolAddress(&p, g_w1l); w1l0=(bf*)p;    w1l1=w1l0+HIDN*DIMN;
      cudaGetSymbolAddress(&p, g_w2f); w2f0=(float*)p; w2f1=w2f0+DIMN*HIDN;
      cudaGetSymbolAddress(&p, g_w2h); w2h0=(bf*)p;    w2h1=w2h0+DIMN*HIDN;
      cudaGetSymbolAddress(&p, g_w2l); w2l0=(bf*)p;    w2l1=w2l0+DIMN*HIDN;
    }

    // launch 0: fused splits + momentum zeroing
    prep_k<<<20480, 256>>>(x, Wk, Wv, Wq, Wout, W1, W2);
    // launches 1,2: gates
    gate_tok_k<<<NTOK, 256>>>(x, Wlr, blr, Wdec, bdec, Wmom, bmom);
    gate_chunk_k<<<NCH, 256>>>();
    // launch 3: fused projections (k,q,v)
    proj_k<<<dim3(DIMN/64, NTOK/64, 3),128,SM_A64>>>();
    // launch 4: fused l2norm (k+q)
    l2norm2_k<<<2*NTOK,256>>>();

    for (int ch = 0; ch < NCH; ++ch) {
        size_t co = (size_t)ch*BC*DIMN;
        const bf *kth = kph+co, *ktl = kpl+co;
        const bf *qth = qph+co, *qtl = qpl+co;
        const bf *vth = vph+co, *vtl = vpl+co;
        int wi = ch & 1;
        int ri = 1 - wi;
        const float* w1o = (ch == 0) ? W1 : (ri ? w1f1 : w1f0);
        const float* w2o = (ch == 0) ? W2 : (ri ? w2f1 : w2f0);
        const bf *w1rh = ri ? w1h1 : w1h0, *w1rl = ri ? w1l1 : w1l0;
        const bf *w2rh = ri ? w2h1 : w2h0, *w2rl = ri ? w2l1 : w2l0;
        float* w1n = wi ? w1f1 : w1f0;
        float* w2n = wi ? w2f1 : w2f0;
        bf *w1nh = wi ? w1h1 : w1h0, *w1nl = wi ? w1l1 : w1l0;
        bf *w2nh = wi ? w2h1 : w2h0, *w2nl = wi ? w2l1 : w2l0;
        const float* gp3 = gch + ch*3;

        // forward + grads on stream 0
        mgemm_k<32,64,true,true,1><<<dim3(HIDN/64, BC/32),128,SM_A32>>>(
            kth,ktl,DIMN, w1rh,w1rl,DIMN, h1,a1h,a1l,HIDN, DIMN,
            nullptr,nullptr,nullptr,nullptr, nullptr,0.f,0);
        mgemm_k<32,64,true,true,2><<<dim3(DIMN/64, BC/32),128,SM_A32>>>(
            a1h,a1l,HIDN, w2rh,w2rl,HIDN, nullptr,d2h,d2l,DIMN, HIDN,
            nullptr,vth,vtl,nullptr, nullptr,SCALE_CONST,0);
        mgemm_k<32,64,true,false,3><<<dim3(HIDN/64, BC/32),128,SM_R32>>>(
            d2h,d2l,DIMN, w2rh,w2rl,HIDN, nullptr,d1h,d1l,HIDN, DIMN,
            h1,nullptr,nullptr,nullptr, nullptr,0.f,0);
        // wupd(ch) rewrites weight slot (ch&1): wait until retrieval of ch-2 (same slot) finished
        if (ch >= 2) cudaStreamWaitEvent(0, (ch & 1) ? evB1 : evB0, 0);
        wupd_k<<<(HIDN/64)*(DIMN/64)*2,128,SM_R64>>>(
            kth,ktl, w2n,w2nh,w2nl, w2o, w1n,w1nh,w1nl, w1o, gp3);
        // retrieval on stream 2, overlapped with next chunk's forward
        cudaEventRecord(evA, 0);
        cudaStreamWaitEvent(s2, evA, 0);
        mgemm_k<32,64,true,true,5><<<dim3(HIDN/64, BC/32),128,SM_A32,s2>>>(
            qth,qtl,DIMN, w1nh,w1nl,DIMN, nullptr,aqh,aql,HIDN, DIMN,
            nullptr,nullptr,nullptr,nullptr, nullptr,0.f,0);
        mgemm_k<32,64,true,true,6><<<dim3(DIMN/64, BC/32),128,SM_A32,s2>>>(
            aqh,aql,HIDN, w2nh,w2nl,HIDN, nullptr,yh,yl,DIMN, HIDN,
            nullptr,nullptr,nullptr,nullptr, nullptr,0.f,ch*CHK);
        cudaEventRecord((ch & 1) ? evB1 : evB0, s2);
    }

    // join retrieval stream, then output projection
    cudaStreamWaitEvent(0, ((NCH-1) & 1) ? evB1 : evB0, 0);
    mgemm_k<64,64,true,true,0><<<dim3(DIMN/64, NTOK/64),128,SM_A64>>>(
        yh,yl,DIMN, woh,wol,DIMN, out,nullptr,nullptr,DIMN, DIMN,
        nullptr,nullptr,nullptr,nullptr, nullptr,0.f,0);
}